// round 12
// baseline (speedup 1.0000x reference)
#include <cuda_runtime.h>
#include <cuda_bf16.h>
#include <cstdint>

// Problem constants
#define BATCH 2
#define SEQ   2048
#define DIN   1024
#define DOUT  1024
#define NHEAD 16
#define HDIM  64
#define M_ROWS (BATCH * SEQ)          // 4096
#define QKV_COLS (3 * DOUT)           // 3072

// Scratch (device globals; no runtime allocation allowed)
__device__ float g_qkv[(size_t)M_ROWS * QKV_COLS];   // tf32-rounded, Q pre-scaled
__device__ float g_y[(size_t)M_ROWS * DOUT];         // tf32-rounded

// ---------------------------------------------------------------------------
// PTX helpers
// ---------------------------------------------------------------------------
__device__ __forceinline__ void cp_async16(void* smem, const void* gmem) {
    uint32_t s = (uint32_t)__cvta_generic_to_shared(smem);
    asm volatile("cp.async.cg.shared.global [%0], [%1], 16;\n" :: "r"(s), "l"(gmem));
}
__device__ __forceinline__ void cp_commit() {
    asm volatile("cp.async.commit_group;\n");
}
template <int N>
__device__ __forceinline__ void cp_wait() {
    asm volatile("cp.async.wait_group %0;\n" :: "n"(N));
}
__device__ __forceinline__ uint32_t f2tf(float f) {
    uint32_t r;
    asm("cvt.rna.tf32.f32 %0, %1;" : "=r"(r) : "f"(f));
    return r;
}
__device__ __forceinline__ float tf32r(float f) {
    return __uint_as_float(f2tf(f));
}
__device__ __forceinline__ float ex2(float x) {
    float y;
    asm("ex2.approx.f32 %0, %1;" : "=f"(y) : "f"(x));
    return y;
}
__device__ __forceinline__ float rcp(float x) {
    float y;
    asm("rcp.approx.f32 %0, %1;" : "=f"(y) : "f"(x));
    return y;
}
__device__ __forceinline__ void mma_tf32(float c[4],
                                         const uint32_t a[4],
                                         const uint32_t b[2]) {
    asm volatile(
        "mma.sync.aligned.m16n8k8.row.col.f32.tf32.tf32.f32 "
        "{%0,%1,%2,%3}, {%4,%5,%6,%7}, {%8,%9}, {%0,%1,%2,%3};\n"
        : "+f"(c[0]), "+f"(c[1]), "+f"(c[2]), "+f"(c[3])
        : "r"(a[0]), "r"(a[1]), "r"(a[2]), "r"(a[3]), "r"(b[0]), "r"(b[1]));
}

// ---------------------------------------------------------------------------
// TF32 tensor-core GEMM: C[M,N] = A[M,K] @ B[N,K]^T (+bias)
// OCCUPANCY VERSION: BM=64, BN=128, warp tile 32x32, 256 threads,
// 3 CTAs/SM (launch_bounds(256,3): regs<=85, smem 45KB*3=135KB) ->
// 6 warps/SMSP to cover LDS->cvt->mma dependency stalls.
// 3-stage cp.async pipeline, one __syncthreads per K-stage. Stride 20.
// ---------------------------------------------------------------------------
#define BM 64
#define BN 128
#define BK 16
#define GST 20                               // BK + 4 pad
#define ASTAGE (BM * GST)                    // 1280 floats
#define BSTAGE (BN * GST)                    // 2560 floats
#define STAGE_FLOATS (ASTAGE + BSTAGE)       // 3840 floats
#define NSTAGE 3
#define GEMM_SMEM_BYTES (NSTAGE * STAGE_FLOATS * 4)   // 46080 B

template <bool BIAS, bool ROUND, bool QSCALE>
__global__ __launch_bounds__(256, 3) void gemm_tf32_nt(
    const float* __restrict__ A, const float* __restrict__ B,
    const float* __restrict__ bias, float* __restrict__ C,
    int M, int N, int K)
{
    extern __shared__ float sm[];

    const int tid  = threadIdx.x;
    const int lane = tid & 31;
    const int warp = tid >> 5;
    const int wm = warp & 1;          // 2 warps along M (32 rows each)
    const int wn = warp >> 1;         // 4 warps along N (32 cols each)
    const int g  = lane >> 2;
    const int tg = lane & 3;

    const int bm = blockIdx.y * BM;
    const int bn = blockIdx.x * BN;

    // loaders: A = 256 16B units (1/thread), B = 512 units (2/thread)
    const int ar = tid >> 2;            // 0..63
    const int ac = (tid & 3) * 4;
    const int br0 = tid >> 1;           // 0..127  (unit t*2? no: unit u=t)
    // B units: u in [0,512); thread handles u=tid and u=tid+256
    const int b0r = tid >> 2;           // rows 0..63 for u=tid
    const int b0c = (tid & 3) * 4;
    const int b1r = (tid + 256) >> 2;   // rows 64..127
    const int b1c = (tid & 3) * 4;

    const float* Ag  = A + (size_t)(bm + ar) * K + ac;
    const float* Bg0 = B + (size_t)(bn + b0r) * K + b0c;
    const float* Bg1 = B + (size_t)(bn + b1r) * K + b1c;

    auto load_stage = [&](int s, int ko) {
        float* As = sm + s * STAGE_FLOATS;
        float* Bs = As + ASTAGE;
        cp_async16(As + ar * GST + ac,   Ag  + ko);
        cp_async16(Bs + b0r * GST + b0c, Bg0 + ko);
        cp_async16(Bs + b1r * GST + b1c, Bg1 + ko);
        cp_commit();
    };

    float acc[2][4][4];
#pragma unroll
    for (int mt = 0; mt < 2; mt++)
#pragma unroll
        for (int nt = 0; nt < 4; nt++)
#pragma unroll
            for (int i = 0; i < 4; i++) acc[mt][nt][i] = 0.f;

    const int nstages = K / BK;

    load_stage(0, 0);
    load_stage(1, BK);

    for (int it = 0; it < nstages; it++) {
        if (it + 1 < nstages) cp_wait<1>();
        else                  cp_wait<0>();
        __syncthreads();

        if (it + 2 < nstages)
            load_stage((it + 2) % NSTAGE, (it + 2) * BK);

        const float* Ab = sm + (it % NSTAGE) * STAGE_FLOATS;
        const float* Bb = Ab + ASTAGE;

#pragma unroll
        for (int ks = 0; ks < BK; ks += 8) {
            uint32_t af[2][4], bf[4][2];
#pragma unroll
            for (int mt = 0; mt < 2; mt++) {
                const int m = wm * 32 + mt * 16;
                af[mt][0] = f2tf(Ab[(m + g) * GST + ks + tg]);
                af[mt][1] = f2tf(Ab[(m + g + 8) * GST + ks + tg]);
                af[mt][2] = f2tf(Ab[(m + g) * GST + ks + tg + 4]);
                af[mt][3] = f2tf(Ab[(m + g + 8) * GST + ks + tg + 4]);
            }
#pragma unroll
            for (int nt = 0; nt < 4; nt++) {
                const int n = wn * 32 + nt * 8;
                bf[nt][0] = f2tf(Bb[(n + g) * GST + ks + tg]);
                bf[nt][1] = f2tf(Bb[(n + g) * GST + ks + tg + 4]);
            }
#pragma unroll
            for (int mt = 0; mt < 2; mt++)
#pragma unroll
                for (int nt = 0; nt < 4; nt++)
                    mma_tf32(acc[mt][nt], af[mt], bf[nt]);
        }
    }

    const float qsc = 0.125f * 1.4426950408889634f;

#pragma unroll
    for (int mt = 0; mt < 2; mt++) {
        const int row0 = bm + wm * 32 + mt * 16 + g;
#pragma unroll
        for (int nt = 0; nt < 4; nt++) {
            const int col = bn + wn * 32 + nt * 8 + 2 * tg;
            float v0 = acc[mt][nt][0], v1 = acc[mt][nt][1];
            float v2 = acc[mt][nt][2], v3 = acc[mt][nt][3];
            if (QSCALE && col < DOUT) { v0 *= qsc; v1 *= qsc; v2 *= qsc; v3 *= qsc; }
            if (BIAS) {
                float b0 = bias[col], b1 = bias[col + 1];
                v0 += b0; v1 += b1; v2 += b0; v3 += b1;
            }
            if (ROUND) {
                v0 = tf32r(v0); v1 = tf32r(v1);
                v2 = tf32r(v2); v3 = tf32r(v3);
            }
            *(float2*)(C + (size_t)row0 * N + col) = make_float2(v0, v1);
            *(float2*)(C + (size_t)(row0 + 8) * N + col) = make_float2(v2, v3);
        }
    }
}

// ---------------------------------------------------------------------------
// Flash attention (causal), tf32 mma — R11 exact (measured best).
// ---------------------------------------------------------------------------
#define KS_ST 68
#define VS_ST 72
#define FLASH_SMEM_BYTES ((2*64*KS_ST + 2*64*VS_ST + 128*KS_ST) * 4)

__global__ __launch_bounds__(256, 1) void flash_mma_kernel(
    const float* __restrict__ qkv, float* __restrict__ y)
{
    extern __shared__ float sm[];
    float (*Ks)[64][KS_ST] = (float(*)[64][KS_ST])sm;
    float (*Vs)[64][VS_ST] = (float(*)[64][VS_ST])(sm + 2 * 64 * KS_ST);
    float (*Ps)[KS_ST]     = (float(*)[KS_ST])(sm + 2 * 64 * KS_ST + 2 * 64 * VS_ST);

    const int qi = (int)gridDim.x - 1 - (int)blockIdx.x;  // heavy tiles first
    const int bh = blockIdx.y;
    const int b  = bh >> 4;
    const int h  = bh & 15;
    const int qbase = qi * 128;

    const float* base = qkv + (size_t)b * SEQ * QKV_COLS;
    const int hoff = h * HDIM;

    const int tid  = threadIdx.x;
    const int lane = tid & 31;
    const int warp = tid >> 5;
    const int g  = lane >> 2;
    const int tg = lane & 3;
    const int w16 = warp * 16;

    for (int i = tid; i < 128 * 16; i += 256) {
        int r  = i >> 4;
        int c4 = (i & 15) * 4;
        float4 v = *(const float4*)(base + (size_t)(qbase + r) * QKV_COLS + hoff + c4);
        *(float4*)&Ps[r][c4] = v;
    }
    __syncthreads();

    uint32_t aq[8][4];
#pragma unroll
    for (int ks = 0; ks < 8; ks++) {
        aq[ks][0] = __float_as_uint(Ps[w16 + g][ks * 8 + tg]);
        aq[ks][1] = __float_as_uint(Ps[w16 + g + 8][ks * 8 + tg]);
        aq[ks][2] = __float_as_uint(Ps[w16 + g][ks * 8 + tg + 4]);
        aq[ks][3] = __float_as_uint(Ps[w16 + g + 8][ks * 8 + tg + 4]);
    }
    __syncthreads();

    float O[8][4];
#pragma unroll
    for (int n = 0; n < 8; n++)
#pragma unroll
        for (int i = 0; i < 4; i++) O[n][i] = 0.f;
    float m0 = -1e30f, m1 = -1e30f, l0 = 0.f, l1 = 0.f;

    const int njt = 2 * (qi + 1);

    auto prefetch = [&](int jt, int buf) {
        const int jb = jt * 64;
        for (int i = tid; i < 64 * 16; i += 256) {
            int r  = i >> 4;
            int c4 = (i & 15) * 4;
            const float* rowp = base + (size_t)(jb + r) * QKV_COLS + hoff;
            cp_async16(&Ks[buf][r][c4], rowp + DOUT + c4);
            cp_async16(&Vs[buf][r][c4], rowp + 2 * DOUT + c4);
        }
        cp_commit();
    };

    prefetch(0, 0);

    for (int jt = 0; jt < njt; jt++) {
        const int buf = jt & 1;
        if (jt + 1 < njt) {
            prefetch(jt + 1, (jt + 1) & 1);
            cp_wait<1>();
        } else {
            cp_wait<0>();
        }
        __syncthreads();

        float S[8][4];
#pragma unroll
        for (int n = 0; n < 8; n++)
#pragma unroll
            for (int i = 0; i < 4; i++) S[n][i] = 0.f;

#pragma unroll
        for (int ks = 0; ks < 8; ks++) {
#pragma unroll
            for (int n = 0; n < 8; n++) {
                uint32_t kb[2];
                kb[0] = __float_as_uint(Ks[buf][n * 8 + g][ks * 8 + tg]);
                kb[1] = __float_as_uint(Ks[buf][n * 8 + g][ks * 8 + tg + 4]);
                mma_tf32(S[n], aq[ks], kb);
            }
        }

        if (jt >= 2 * qi) {
            const int r0 = qbase + w16 + g;
            const int r1 = r0 + 8;
            const int cb = jt * 64 + 2 * tg;
#pragma unroll
            for (int n = 0; n < 8; n++) {
                const int c0 = cb + n * 8;
                if (c0 > r0)     S[n][0] = -1e30f;
                if (c0 + 1 > r0) S[n][1] = -1e30f;
                if (c0 > r1)     S[n][2] = -1e30f;
                if (c0 + 1 > r1) S[n][3] = -1e30f;
            }
        }

        float rm0 = -1e30f, rm1 = -1e30f;
#pragma unroll
        for (int n = 0; n < 8; n++) {
            rm0 = fmaxf(rm0, fmaxf(S[n][0], S[n][1]));
            rm1 = fmaxf(rm1, fmaxf(S[n][2], S[n][3]));
        }
        rm0 = fmaxf(rm0, __shfl_xor_sync(0xffffffffu, rm0, 1));
        rm0 = fmaxf(rm0, __shfl_xor_sync(0xffffffffu, rm0, 2));
        rm1 = fmaxf(rm1, __shfl_xor_sync(0xffffffffu, rm1, 1));
        rm1 = fmaxf(rm1, __shfl_xor_sync(0xffffffffu, rm1, 2));

        const float mn0 = fmaxf(m0, rm0);
        const float mn1 = fmaxf(m1, rm1);
        const float corr0 = ex2(m0 - mn0);
        const float corr1 = ex2(m1 - mn1);
        m0 = mn0; m1 = mn1;

        float rs0 = 0.f, rs1 = 0.f;
#pragma unroll
        for (int n = 0; n < 8; n++) {
            float p0 = ex2(S[n][0] - mn0);
            float p1 = ex2(S[n][1] - mn0);
            float p2 = ex2(S[n][2] - mn1);
            float p3 = ex2(S[n][3] - mn1);
            rs0 += p0 + p1;
            rs1 += p2 + p3;
            O[n][0] *= corr0; O[n][1] *= corr0;
            O[n][2] *= corr1; O[n][3] *= corr1;
            *(float2*)&Ps[w16 + g][n * 8 + 2 * tg]     = make_float2(tf32r(p0), tf32r(p1));
            *(float2*)&Ps[w16 + g + 8][n * 8 + 2 * tg] = make_float2(tf32r(p2), tf32r(p3));
        }
        rs0 += __shfl_xor_sync(0xffffffffu, rs0, 1);
        rs0 += __shfl_xor_sync(0xffffffffu, rs0, 2);
        rs1 += __shfl_xor_sync(0xffffffffu, rs1, 1);
        rs1 += __shfl_xor_sync(0xffffffffu, rs1, 2);
        l0 = l0 * corr0 + rs0;
        l1 = l1 * corr1 + rs1;

        __syncwarp();

#pragma unroll
        for (int ks = 0; ks < 8; ks++) {
            uint32_t pa[4];
            pa[0] = __float_as_uint(Ps[w16 + g][ks * 8 + tg]);
            pa[1] = __float_as_uint(Ps[w16 + g + 8][ks * 8 + tg]);
            pa[2] = __float_as_uint(Ps[w16 + g][ks * 8 + tg + 4]);
            pa[3] = __float_as_uint(Ps[w16 + g + 8][ks * 8 + tg + 4]);
#pragma unroll
            for (int n = 0; n < 8; n++) {
                uint32_t vb[2];
                vb[0] = __float_as_uint(Vs[buf][ks * 8 + tg][n * 8 + g]);
                vb[1] = __float_as_uint(Vs[buf][ks * 8 + tg + 4][n * 8 + g]);
                mma_tf32(O[n], pa, vb);
            }
        }
        __syncthreads();
    }

    const float inv0 = rcp(l0);
    const float inv1 = rcp(l1);
    const int r0 = qbase + w16 + g;
    float* yr0 = y + (size_t)b * SEQ * DOUT + (size_t)r0 * DOUT + hoff;
    float* yr1 = yr0 + 8 * DOUT;
#pragma unroll
    for (int n = 0; n < 8; n++) {
        const int c = n * 8 + 2 * tg;
        *(float2*)(yr0 + c) = make_float2(tf32r(O[n][0] * inv0), tf32r(O[n][1] * inv0));
        *(float2*)(yr1 + c) = make_float2(tf32r(O[n][2] * inv1), tf32r(O[n][3] * inv1));
    }
}

// ---------------------------------------------------------------------------
extern "C" void kernel_launch(void* const* d_in, const int* in_sizes, int n_in,
                              void* d_out, int out_size)
{
    const float* x     = (const float*)d_in[0];
    const float* w_qkv = (const float*)d_in[1];
    const float* w_out = (const float*)d_in[2];
    const float* b_out = (const float*)d_in[3];
    float* out = (float*)d_out;

    float *qkv_ptr, *y_ptr;
    cudaGetSymbolAddress((void**)&qkv_ptr, g_qkv);
    cudaGetSymbolAddress((void**)&y_ptr, g_y);

    cudaFuncSetAttribute(gemm_tf32_nt<false, true, true>,
                         cudaFuncAttributeMaxDynamicSharedMemorySize,
                         GEMM_SMEM_BYTES);
    cudaFuncSetAttribute(gemm_tf32_nt<true, false, false>,
                         cudaFuncAttributeMaxDynamicSharedMemorySize,
                         GEMM_SMEM_BYTES);
    cudaFuncSetAttribute(flash_mma_kernel,
                         cudaFuncAttributeMaxDynamicSharedMemorySize,
                         FLASH_SMEM_BYTES);

    // 1) QKV projection (output tf32-rounded, Q pre-scaled by 0.125*log2e)
    gemm_tf32_nt<false, true, true>
        <<<dim3(QKV_COLS / BN, M_ROWS / BM), 256, GEMM_SMEM_BYTES>>>(
        x, w_qkv, nullptr, qkv_ptr, M_ROWS, QKV_COLS, DIN);

    // 2) Flash attention (y stored tf32-rounded)
    flash_mma_kernel<<<dim3(SEQ / 128, BATCH * NHEAD), 256, FLASH_SMEM_BYTES>>>(
        qkv_ptr, y_ptr);

    // 3) Output projection + bias (final fp32 output)
    gemm_tf32_nt<true, false, false>
        <<<dim3(DOUT / BN, M_ROWS / BM), 256, GEMM_SMEM_BYTES>>>(
        y_ptr, w_out, b_out, out, M_ROWS, DOUT, DOUT);
}

// round 13
// speedup vs baseline: 1.2317x; 1.2317x over previous
#include <cuda_runtime.h>
#include <cuda_bf16.h>
#include <cstdint>

// Problem constants
#define BATCH 2
#define SEQ   2048
#define DIN   1024
#define DOUT  1024
#define NHEAD 16
#define HDIM  64
#define M_ROWS (BATCH * SEQ)          // 4096
#define QKV_COLS (3 * DOUT)           // 3072

// Scratch (device globals; no runtime allocation allowed)
__device__ float g_qkv[(size_t)M_ROWS * QKV_COLS];   // tf32-rounded, Q pre-scaled
__device__ float g_y[(size_t)M_ROWS * DOUT];         // tf32-rounded

// ---------------------------------------------------------------------------
// PTX helpers
// ---------------------------------------------------------------------------
__device__ __forceinline__ void cp_async16(void* smem, const void* gmem) {
    uint32_t s = (uint32_t)__cvta_generic_to_shared(smem);
    asm volatile("cp.async.cg.shared.global [%0], [%1], 16;\n" :: "r"(s), "l"(gmem));
}
__device__ __forceinline__ void cp_commit() {
    asm volatile("cp.async.commit_group;\n");
}
template <int N>
__device__ __forceinline__ void cp_wait() {
    asm volatile("cp.async.wait_group %0;\n" :: "n"(N));
}
__device__ __forceinline__ uint32_t f2tf(float f) {
    uint32_t r;
    asm("cvt.rna.tf32.f32 %0, %1;" : "=r"(r) : "f"(f));
    return r;
}
__device__ __forceinline__ float tf32r(float f) {
    return __uint_as_float(f2tf(f));
}
__device__ __forceinline__ float ex2(float x) {
    float y;
    asm("ex2.approx.f32 %0, %1;" : "=f"(y) : "f"(x));
    return y;
}
__device__ __forceinline__ float rcp(float x) {
    float y;
    asm("rcp.approx.f32 %0, %1;" : "=f"(y) : "f"(x));
    return y;
}
__device__ __forceinline__ void mma_tf32(float c[4],
                                         const uint32_t a[4],
                                         const uint32_t b[2]) {
    asm volatile(
        "mma.sync.aligned.m16n8k8.row.col.f32.tf32.tf32.f32 "
        "{%0,%1,%2,%3}, {%4,%5,%6,%7}, {%8,%9}, {%0,%1,%2,%3};\n"
        : "+f"(c[0]), "+f"(c[1]), "+f"(c[2]), "+f"(c[3])
        : "r"(a[0]), "r"(a[1]), "r"(a[2]), "r"(a[3]), "r"(b[0]), "r"(b[1]));
}

// ---------------------------------------------------------------------------
// TF32 tensor-core GEMM: C[M,N] = A[M,K] @ B[N,K]^T (+bias)
// R7/R11 EXACT (measured best 197.6us): 3-stage cp.async, one barrier per
// K-stage, BK=16, stride 20, in-loop cvt.rna fragment loads.
// ---------------------------------------------------------------------------
#define BM 128
#define BN 128
#define BK 16
#define GST 20                       // BK + 4 pad
#define STAGE_FLOATS (2 * BM * GST)  // 5120 floats
#define NSTAGE 3
#define GEMM_SMEM_BYTES (NSTAGE * STAGE_FLOATS * 4)   // 61440 B

template <bool BIAS, bool ROUND, bool QSCALE>
__global__ __launch_bounds__(256, 2) void gemm_tf32_nt(
    const float* __restrict__ A, const float* __restrict__ B,
    const float* __restrict__ bias, float* __restrict__ C,
    int M, int N, int K)
{
    extern __shared__ float sm[];

    const int tid  = threadIdx.x;
    const int lane = tid & 31;
    const int warp = tid >> 5;
    const int wm = warp & 1;          // 2 warps along M (64 rows each)
    const int wn = warp >> 1;         // 4 warps along N (32 cols each)
    const int g  = lane >> 2;
    const int tg = lane & 3;

    const int bm = blockIdx.y * BM;
    const int bn = blockIdx.x * BN;

    const int ldr = tid >> 2;          // 0..63
    const int ldc = (tid & 3) * 4;     // 0,4,8,12

    const float* Ag0 = A + (size_t)(bm + ldr) * K + ldc;
    const float* Ag1 = A + (size_t)(bm + ldr + 64) * K + ldc;
    const float* Bg0 = B + (size_t)(bn + ldr) * K + ldc;
    const float* Bg1 = B + (size_t)(bn + ldr + 64) * K + ldc;

    auto load_stage = [&](int s, int ko) {
        float* As = sm + s * STAGE_FLOATS;
        float* Bs = As + BM * GST;
        cp_async16(As + ldr * GST + ldc,        Ag0 + ko);
        cp_async16(As + (ldr + 64) * GST + ldc, Ag1 + ko);
        cp_async16(Bs + ldr * GST + ldc,        Bg0 + ko);
        cp_async16(Bs + (ldr + 64) * GST + ldc, Bg1 + ko);
        cp_commit();
    };

    float acc[4][4][4];
#pragma unroll
    for (int mt = 0; mt < 4; mt++)
#pragma unroll
        for (int nt = 0; nt < 4; nt++)
#pragma unroll
            for (int i = 0; i < 4; i++) acc[mt][nt][i] = 0.f;

    const int nstages = K / BK;

    load_stage(0, 0);
    load_stage(1, BK);

    for (int it = 0; it < nstages; it++) {
        if (it + 1 < nstages) cp_wait<1>();
        else                  cp_wait<0>();
        __syncthreads();

        if (it + 2 < nstages)
            load_stage((it + 2) % NSTAGE, (it + 2) * BK);

        const float* Ab = sm + (it % NSTAGE) * STAGE_FLOATS;
        const float* Bb = Ab + BM * GST;

#pragma unroll
        for (int ks = 0; ks < BK; ks += 8) {
            uint32_t af[4][4], bf[4][2];
#pragma unroll
            for (int mt = 0; mt < 4; mt++) {
                const int m = wm * 64 + mt * 16;
                af[mt][0] = f2tf(Ab[(m + g) * GST + ks + tg]);
                af[mt][1] = f2tf(Ab[(m + g + 8) * GST + ks + tg]);
                af[mt][2] = f2tf(Ab[(m + g) * GST + ks + tg + 4]);
                af[mt][3] = f2tf(Ab[(m + g + 8) * GST + ks + tg + 4]);
            }
#pragma unroll
            for (int nt = 0; nt < 4; nt++) {
                const int n = wn * 32 + nt * 8;
                bf[nt][0] = f2tf(Bb[(n + g) * GST + ks + tg]);
                bf[nt][1] = f2tf(Bb[(n + g) * GST + ks + tg + 4]);
            }
#pragma unroll
            for (int mt = 0; mt < 4; mt++)
#pragma unroll
                for (int nt = 0; nt < 4; nt++)
                    mma_tf32(acc[mt][nt], af[mt], bf[nt]);
        }
    }

    const float qsc = 0.125f * 1.4426950408889634f;

#pragma unroll
    for (int mt = 0; mt < 4; mt++) {
        const int row0 = bm + wm * 64 + mt * 16 + g;
#pragma unroll
        for (int nt = 0; nt < 4; nt++) {
            const int col = bn + wn * 32 + nt * 8 + 2 * tg;
            float v0 = acc[mt][nt][0], v1 = acc[mt][nt][1];
            float v2 = acc[mt][nt][2], v3 = acc[mt][nt][3];
            if (QSCALE && col < DOUT) { v0 *= qsc; v1 *= qsc; v2 *= qsc; v3 *= qsc; }
            if (BIAS) {
                float b0 = bias[col], b1 = bias[col + 1];
                v0 += b0; v1 += b1; v2 += b0; v3 += b1;
            }
            if (ROUND) {
                v0 = tf32r(v0); v1 = tf32r(v1);
                v2 = tf32r(v2); v3 = tf32r(v3);
            }
            *(float2*)(C + (size_t)row0 * N + col) = make_float2(v0, v1);
            *(float2*)(C + (size_t)(row0 + 8) * N + col) = make_float2(v2, v3);
        }
    }
}

// ---------------------------------------------------------------------------
// Flash attention (causal), tf32 mma.
// NEW: P@V consumes the S/P c-fragment DIRECTLY as an A-fragment via a
// kv-relabel (mma k-slot sigma(tg)=2tg, sigma(tg+4)=2tg+1 applied to BOTH
// P columns and V rows -> same sum, no SMEM staging of P, no syncwarp).
// Vs stride 68: V B-fragment bank = (8tg + 8nn + g) mod 32, conflict-free.
// ---------------------------------------------------------------------------
#define KS_ST 68
#define VS_ST 68
#define FLASH_SMEM_BYTES ((2*64*KS_ST + 2*64*VS_ST + 128*68) * 4)

__global__ __launch_bounds__(256, 1) void flash_mma_kernel(
    const float* __restrict__ qkv, float* __restrict__ y)
{
    extern __shared__ float sm[];
    float (*Ks)[64][KS_ST] = (float(*)[64][KS_ST])sm;
    float (*Vs)[64][VS_ST] = (float(*)[64][VS_ST])(sm + 2 * 64 * KS_ST);
    float (*Qs)[68]        = (float(*)[68])(sm + 2 * 64 * KS_ST + 2 * 64 * VS_ST);

    const int qi = (int)gridDim.x - 1 - (int)blockIdx.x;  // heavy tiles first
    const int bh = blockIdx.y;
    const int b  = bh >> 4;
    const int h  = bh & 15;
    const int qbase = qi * 128;

    const float* base = qkv + (size_t)b * SEQ * QKV_COLS;
    const int hoff = h * HDIM;

    const int tid  = threadIdx.x;
    const int lane = tid & 31;
    const int warp = tid >> 5;
    const int g  = lane >> 2;
    const int tg = lane & 3;
    const int w16 = warp * 16;

    for (int i = tid; i < 128 * 16; i += 256) {
        int r  = i >> 4;
        int c4 = (i & 15) * 4;
        float4 v = *(const float4*)(base + (size_t)(qbase + r) * QKV_COLS + hoff + c4);
        *(float4*)&Qs[r][c4] = v;
    }
    __syncthreads();

    uint32_t aq[8][4];
#pragma unroll
    for (int ks = 0; ks < 8; ks++) {
        aq[ks][0] = __float_as_uint(Qs[w16 + g][ks * 8 + tg]);
        aq[ks][1] = __float_as_uint(Qs[w16 + g + 8][ks * 8 + tg]);
        aq[ks][2] = __float_as_uint(Qs[w16 + g][ks * 8 + tg + 4]);
        aq[ks][3] = __float_as_uint(Qs[w16 + g + 8][ks * 8 + tg + 4]);
    }
    __syncthreads();

    float O[8][4];
#pragma unroll
    for (int n = 0; n < 8; n++)
#pragma unroll
        for (int i = 0; i < 4; i++) O[n][i] = 0.f;
    float m0 = -1e30f, m1 = -1e30f, l0 = 0.f, l1 = 0.f;

    const int njt = 2 * (qi + 1);

    auto prefetch = [&](int jt, int buf) {
        const int jb = jt * 64;
        for (int i = tid; i < 64 * 16; i += 256) {
            int r  = i >> 4;
            int c4 = (i & 15) * 4;
            const float* rowp = base + (size_t)(jb + r) * QKV_COLS + hoff;
            cp_async16(&Ks[buf][r][c4], rowp + DOUT + c4);
            cp_async16(&Vs[buf][r][c4], rowp + 2 * DOUT + c4);
        }
        cp_commit();
    };

    prefetch(0, 0);

    for (int jt = 0; jt < njt; jt++) {
        const int buf = jt & 1;
        if (jt + 1 < njt) {
            prefetch(jt + 1, (jt + 1) & 1);
            cp_wait<1>();
        } else {
            cp_wait<0>();
        }
        __syncthreads();

        // ---- S = Qhat @ K^T ----
        float S[8][4];
#pragma unroll
        for (int n = 0; n < 8; n++)
#pragma unroll
            for (int i = 0; i < 4; i++) S[n][i] = 0.f;

#pragma unroll
        for (int ks = 0; ks < 8; ks++) {
#pragma unroll
            for (int n = 0; n < 8; n++) {
                uint32_t kb[2];
                kb[0] = __float_as_uint(Ks[buf][n * 8 + g][ks * 8 + tg]);
                kb[1] = __float_as_uint(Ks[buf][n * 8 + g][ks * 8 + tg + 4]);
                mma_tf32(S[n], aq[ks], kb);
            }
        }

        // ---- causal mask ----
        if (jt >= 2 * qi) {
            const int r0 = qbase + w16 + g;
            const int r1 = r0 + 8;
            const int cb = jt * 64 + 2 * tg;
#pragma unroll
            for (int n = 0; n < 8; n++) {
                const int c0 = cb + n * 8;
                if (c0 > r0)     S[n][0] = -1e30f;
                if (c0 + 1 > r0) S[n][1] = -1e30f;
                if (c0 > r1)     S[n][2] = -1e30f;
                if (c0 + 1 > r1) S[n][3] = -1e30f;
            }
        }

        // ---- online softmax (base-2); P written back into S registers ----
        float rm0 = -1e30f, rm1 = -1e30f;
#pragma unroll
        for (int n = 0; n < 8; n++) {
            rm0 = fmaxf(rm0, fmaxf(S[n][0], S[n][1]));
            rm1 = fmaxf(rm1, fmaxf(S[n][2], S[n][3]));
        }
        rm0 = fmaxf(rm0, __shfl_xor_sync(0xffffffffu, rm0, 1));
        rm0 = fmaxf(rm0, __shfl_xor_sync(0xffffffffu, rm0, 2));
        rm1 = fmaxf(rm1, __shfl_xor_sync(0xffffffffu, rm1, 1));
        rm1 = fmaxf(rm1, __shfl_xor_sync(0xffffffffu, rm1, 2));

        const float mn0 = fmaxf(m0, rm0);
        const float mn1 = fmaxf(m1, rm1);
        const float corr0 = ex2(m0 - mn0);
        const float corr1 = ex2(m1 - mn1);
        m0 = mn0; m1 = mn1;

        float rs0 = 0.f, rs1 = 0.f;
#pragma unroll
        for (int n = 0; n < 8; n++) {
            float p0 = ex2(S[n][0] - mn0);
            float p1 = ex2(S[n][1] - mn0);
            float p2 = ex2(S[n][2] - mn1);
            float p3 = ex2(S[n][3] - mn1);
            rs0 += p0 + p1;
            rs1 += p2 + p3;
            O[n][0] *= corr0; O[n][1] *= corr0;
            O[n][2] *= corr1; O[n][3] *= corr1;
            S[n][0] = p0; S[n][1] = p1; S[n][2] = p2; S[n][3] = p3;
        }
        rs0 += __shfl_xor_sync(0xffffffffu, rs0, 1);
        rs0 += __shfl_xor_sync(0xffffffffu, rs0, 2);
        rs1 += __shfl_xor_sync(0xffffffffu, rs1, 1);
        rs1 += __shfl_xor_sync(0xffffffffu, rs1, 2);
        l0 = l0 * corr0 + rs0;
        l1 = l1 * corr1 + rs1;

        // ---- O += P @ V, P directly from registers (kv relabeled) ----
        // A-fragment slots: a0=P[g][2tg], a1=P[g+8][2tg],
        //                   a2=P[g][2tg+1], a3=P[g+8][2tg+1]
        // B rows follow the same relabel: V rows n*8+2tg, n*8+2tg+1.
#pragma unroll
        for (int n = 0; n < 8; n++) {
            uint32_t pa[4];
            pa[0] = f2tf(S[n][0]);
            pa[1] = f2tf(S[n][2]);
            pa[2] = f2tf(S[n][1]);
            pa[3] = f2tf(S[n][3]);
#pragma unroll
            for (int nn = 0; nn < 8; nn++) {
                uint32_t vb[2];
                vb[0] = __float_as_uint(Vs[buf][n * 8 + 2 * tg][nn * 8 + g]);
                vb[1] = __float_as_uint(Vs[buf][n * 8 + 2 * tg + 1][nn * 8 + g]);
                mma_tf32(O[nn], pa, vb);
            }
        }
        __syncthreads();   // all warps done with buf before it is refilled
    }

    const float inv0 = rcp(l0);
    const float inv1 = rcp(l1);
    const int r0 = qbase + w16 + g;
    float* yr0 = y + (size_t)b * SEQ * DOUT + (size_t)r0 * DOUT + hoff;
    float* yr1 = yr0 + 8 * DOUT;
#pragma unroll
    for (int n = 0; n < 8; n++) {
        const int c = n * 8 + 2 * tg;
        *(float2*)(yr0 + c) = make_float2(tf32r(O[n][0] * inv0), tf32r(O[n][1] * inv0));
        *(float2*)(yr1 + c) = make_float2(tf32r(O[n][2] * inv1), tf32r(O[n][3] * inv1));
    }
}

// ---------------------------------------------------------------------------
extern "C" void kernel_launch(void* const* d_in, const int* in_sizes, int n_in,
                              void* d_out, int out_size)
{
    const float* x     = (const float*)d_in[0];
    const float* w_qkv = (const float*)d_in[1];
    const float* w_out = (const float*)d_in[2];
    const float* b_out = (const float*)d_in[3];
    float* out = (float*)d_out;

    float *qkv_ptr, *y_ptr;
    cudaGetSymbolAddress((void**)&qkv_ptr, g_qkv);
    cudaGetSymbolAddress((void**)&y_ptr, g_y);

    cudaFuncSetAttribute(gemm_tf32_nt<false, true, true>,
                         cudaFuncAttributeMaxDynamicSharedMemorySize,
                         GEMM_SMEM_BYTES);
    cudaFuncSetAttribute(gemm_tf32_nt<true, false, false>,
                         cudaFuncAttributeMaxDynamicSharedMemorySize,
                         GEMM_SMEM_BYTES);
    cudaFuncSetAttribute(flash_mma_kernel,
                         cudaFuncAttributeMaxDynamicSharedMemorySize,
                         FLASH_SMEM_BYTES);

    // 1) QKV projection (output tf32-rounded, Q pre-scaled by 0.125*log2e)
    gemm_tf32_nt<false, true, true>
        <<<dim3(QKV_COLS / BN, M_ROWS / BM), 256, GEMM_SMEM_BYTES>>>(
        x, w_qkv, nullptr, qkv_ptr, M_ROWS, QKV_COLS, DIN);

    // 2) Flash attention (y stored tf32-rounded)
    flash_mma_kernel<<<dim3(SEQ / 128, BATCH * NHEAD), 256, FLASH_SMEM_BYTES>>>(
        qkv_ptr, y_ptr);

    // 3) Output projection + bias (final fp32 output)
    gemm_tf32_nt<true, false, false>
        <<<dim3(DOUT / BN, M_ROWS / BM), 256, GEMM_SMEM_BYTES>>>(
        y_ptr, w_out, b_out, out, M_ROWS, DOUT, DOUT);
}

// round 14
// speedup vs baseline: 1.2384x; 1.0054x over previous
#include <cuda_runtime.h>
#include <cuda_bf16.h>
#include <cstdint>

// Problem constants
#define BATCH 2
#define SEQ   2048
#define DIN   1024
#define DOUT  1024
#define NHEAD 16
#define HDIM  64
#define M_ROWS (BATCH * SEQ)          // 4096
#define QKV_COLS (3 * DOUT)           // 3072

// Scratch (device globals; no runtime allocation allowed)
__device__ float g_qkv[(size_t)M_ROWS * QKV_COLS];   // tf32-rounded, Q pre-scaled
__device__ float g_y[(size_t)M_ROWS * DOUT];         // tf32-rounded

// ---------------------------------------------------------------------------
// PTX helpers
// ---------------------------------------------------------------------------
__device__ __forceinline__ void cp_async16(void* smem, const void* gmem) {
    uint32_t s = (uint32_t)__cvta_generic_to_shared(smem);
    asm volatile("cp.async.cg.shared.global [%0], [%1], 16;\n" :: "r"(s), "l"(gmem));
}
__device__ __forceinline__ void cp_commit() {
    asm volatile("cp.async.commit_group;\n");
}
template <int N>
__device__ __forceinline__ void cp_wait() {
    asm volatile("cp.async.wait_group %0;\n" :: "n"(N));
}
__device__ __forceinline__ uint32_t f2tf(float f) {
    uint32_t r;
    asm("cvt.rna.tf32.f32 %0, %1;" : "=r"(r) : "f"(f));
    return r;
}
__device__ __forceinline__ float tf32r(float f) {
    return __uint_as_float(f2tf(f));
}
__device__ __forceinline__ float ex2(float x) {
    float y;
    asm("ex2.approx.f32 %0, %1;" : "=f"(y) : "f"(x));
    return y;
}
__device__ __forceinline__ float rcp(float x) {
    float y;
    asm("rcp.approx.f32 %0, %1;" : "=f"(y) : "f"(x));
    return y;
}
__device__ __forceinline__ void mma_tf32(float c[4],
                                         const uint32_t a[4],
                                         const uint32_t b[2]) {
    asm volatile(
        "mma.sync.aligned.m16n8k8.row.col.f32.tf32.tf32.f32 "
        "{%0,%1,%2,%3}, {%4,%5,%6,%7}, {%8,%9}, {%0,%1,%2,%3};\n"
        : "+f"(c[0]), "+f"(c[1]), "+f"(c[2]), "+f"(c[3])
        : "r"(a[0]), "r"(a[1]), "r"(a[2]), "r"(a[3]), "r"(b[0]), "r"(b[1]));
}

// ---------------------------------------------------------------------------
// TF32 tensor-core GEMM: C[M,N] = A[M,K] @ B[N,K]^T (+bias)
// R7/R11/R13 EXACT (measured best 196.8us).
// ---------------------------------------------------------------------------
#define BM 128
#define BN 128
#define BK 16
#define GST 20                       // BK + 4 pad
#define STAGE_FLOATS (2 * BM * GST)  // 5120 floats
#define NSTAGE 3
#define GEMM_SMEM_BYTES (NSTAGE * STAGE_FLOATS * 4)   // 61440 B

template <bool BIAS, bool ROUND, bool QSCALE>
__global__ __launch_bounds__(256, 2) void gemm_tf32_nt(
    const float* __restrict__ A, const float* __restrict__ B,
    const float* __restrict__ bias, float* __restrict__ C,
    int M, int N, int K)
{
    extern __shared__ float sm[];

    const int tid  = threadIdx.x;
    const int lane = tid & 31;
    const int warp = tid >> 5;
    const int wm = warp & 1;          // 2 warps along M (64 rows each)
    const int wn = warp >> 1;         // 4 warps along N (32 cols each)
    const int g  = lane >> 2;
    const int tg = lane & 3;

    const int bm = blockIdx.y * BM;
    const int bn = blockIdx.x * BN;

    const int ldr = tid >> 2;          // 0..63
    const int ldc = (tid & 3) * 4;     // 0,4,8,12

    const float* Ag0 = A + (size_t)(bm + ldr) * K + ldc;
    const float* Ag1 = A + (size_t)(bm + ldr + 64) * K + ldc;
    const float* Bg0 = B + (size_t)(bn + ldr) * K + ldc;
    const float* Bg1 = B + (size_t)(bn + ldr + 64) * K + ldc;

    auto load_stage = [&](int s, int ko) {
        float* As = sm + s * STAGE_FLOATS;
        float* Bs = As + BM * GST;
        cp_async16(As + ldr * GST + ldc,        Ag0 + ko);
        cp_async16(As + (ldr + 64) * GST + ldc, Ag1 + ko);
        cp_async16(Bs + ldr * GST + ldc,        Bg0 + ko);
        cp_async16(Bs + (ldr + 64) * GST + ldc, Bg1 + ko);
        cp_commit();
    };

    float acc[4][4][4];
#pragma unroll
    for (int mt = 0; mt < 4; mt++)
#pragma unroll
        for (int nt = 0; nt < 4; nt++)
#pragma unroll
            for (int i = 0; i < 4; i++) acc[mt][nt][i] = 0.f;

    const int nstages = K / BK;

    load_stage(0, 0);
    load_stage(1, BK);

    for (int it = 0; it < nstages; it++) {
        if (it + 1 < nstages) cp_wait<1>();
        else                  cp_wait<0>();
        __syncthreads();

        if (it + 2 < nstages)
            load_stage((it + 2) % NSTAGE, (it + 2) * BK);

        const float* Ab = sm + (it % NSTAGE) * STAGE_FLOATS;
        const float* Bb = Ab + BM * GST;

#pragma unroll
        for (int ks = 0; ks < BK; ks += 8) {
            uint32_t af[4][4], bf[4][2];
#pragma unroll
            for (int mt = 0; mt < 4; mt++) {
                const int m = wm * 64 + mt * 16;
                af[mt][0] = f2tf(Ab[(m + g) * GST + ks + tg]);
                af[mt][1] = f2tf(Ab[(m + g + 8) * GST + ks + tg]);
                af[mt][2] = f2tf(Ab[(m + g) * GST + ks + tg + 4]);
                af[mt][3] = f2tf(Ab[(m + g + 8) * GST + ks + tg + 4]);
            }
#pragma unroll
            for (int nt = 0; nt < 4; nt++) {
                const int n = wn * 32 + nt * 8;
                bf[nt][0] = f2tf(Bb[(n + g) * GST + ks + tg]);
                bf[nt][1] = f2tf(Bb[(n + g) * GST + ks + tg + 4]);
            }
#pragma unroll
            for (int mt = 0; mt < 4; mt++)
#pragma unroll
                for (int nt = 0; nt < 4; nt++)
                    mma_tf32(acc[mt][nt], af[mt], bf[nt]);
        }
    }

    const float qsc = 0.125f * 1.4426950408889634f;

#pragma unroll
    for (int mt = 0; mt < 4; mt++) {
        const int row0 = bm + wm * 64 + mt * 16 + g;
#pragma unroll
        for (int nt = 0; nt < 4; nt++) {
            const int col = bn + wn * 32 + nt * 8 + 2 * tg;
            float v0 = acc[mt][nt][0], v1 = acc[mt][nt][1];
            float v2 = acc[mt][nt][2], v3 = acc[mt][nt][3];
            if (QSCALE && col < DOUT) { v0 *= qsc; v1 *= qsc; v2 *= qsc; v3 *= qsc; }
            if (BIAS) {
                float b0 = bias[col], b1 = bias[col + 1];
                v0 += b0; v1 += b1; v2 += b0; v3 += b1;
            }
            if (ROUND) {
                v0 = tf32r(v0); v1 = tf32r(v1);
                v2 = tf32r(v2); v3 = tf32r(v3);
            }
            *(float2*)(C + (size_t)row0 * N + col) = make_float2(v0, v1);
            *(float2*)(C + (size_t)(row0 + 8) * N + col) = make_float2(v2, v3);
        }
    }
}

// ---------------------------------------------------------------------------
// Flash attention (causal), tf32 mma, register-direct P@V (R13 math).
// NEW: 3-stage K/V pipeline with ONE __syncthreads per kv-tile
// (wait -> barrier -> prefetch(jt+2) -> compute; GEMM-proven pattern).
// SMEM: Ks[3][64][68], Vs[3][64][68], Qs[128][68] = 136KB (1 CTA/SM).
// ---------------------------------------------------------------------------
#define KS_ST 68
#define VS_ST 68
#define FSTAGE (64 * KS_ST + 64 * VS_ST)   // floats per stage (K+V)
#define FNSTAGE 3
#define FLASH_SMEM_BYTES ((FNSTAGE * FSTAGE + 128 * 68) * 4)

__global__ __launch_bounds__(256, 1) void flash_mma_kernel(
    const float* __restrict__ qkv, float* __restrict__ y)
{
    extern __shared__ float sm[];
    float (*Qs)[68] = (float(*)[68])(sm + FNSTAGE * FSTAGE);

    const int qi = (int)gridDim.x - 1 - (int)blockIdx.x;  // heavy tiles first
    const int bh = blockIdx.y;
    const int b  = bh >> 4;
    const int h  = bh & 15;
    const int qbase = qi * 128;

    const float* base = qkv + (size_t)b * SEQ * QKV_COLS;
    const int hoff = h * HDIM;

    const int tid  = threadIdx.x;
    const int lane = tid & 31;
    const int warp = tid >> 5;
    const int g  = lane >> 2;
    const int tg = lane & 3;
    const int w16 = warp * 16;

    for (int i = tid; i < 128 * 16; i += 256) {
        int r  = i >> 4;
        int c4 = (i & 15) * 4;
        float4 v = *(const float4*)(base + (size_t)(qbase + r) * QKV_COLS + hoff + c4);
        *(float4*)&Qs[r][c4] = v;
    }
    __syncthreads();

    uint32_t aq[8][4];
#pragma unroll
    for (int ks = 0; ks < 8; ks++) {
        aq[ks][0] = __float_as_uint(Qs[w16 + g][ks * 8 + tg]);
        aq[ks][1] = __float_as_uint(Qs[w16 + g + 8][ks * 8 + tg]);
        aq[ks][2] = __float_as_uint(Qs[w16 + g][ks * 8 + tg + 4]);
        aq[ks][3] = __float_as_uint(Qs[w16 + g + 8][ks * 8 + tg + 4]);
    }
    // no barrier needed: Qs never rewritten

    float O[8][4];
#pragma unroll
    for (int n = 0; n < 8; n++)
#pragma unroll
        for (int i = 0; i < 4; i++) O[n][i] = 0.f;
    float m0 = -1e30f, m1 = -1e30f, l0 = 0.f, l1 = 0.f;

    const int njt = 2 * (qi + 1);

    auto prefetch = [&](int jt, int stage) {
        const int jb = jt * 64;
        float* Ks = sm + stage * FSTAGE;
        float* Vs = Ks + 64 * KS_ST;
        for (int i = tid; i < 64 * 16; i += 256) {
            int r  = i >> 4;
            int c4 = (i & 15) * 4;
            const float* rowp = base + (size_t)(jb + r) * QKV_COLS + hoff;
            cp_async16(Ks + r * KS_ST + c4, rowp + DOUT + c4);
            cp_async16(Vs + r * VS_ST + c4, rowp + 2 * DOUT + c4);
        }
        cp_commit();
    };

    prefetch(0, 0);
    if (njt > 1) prefetch(1, 1);

    for (int jt = 0; jt < njt; jt++) {
        if (jt + 1 < njt) cp_wait<1>();
        else              cp_wait<0>();
        __syncthreads();   // stage jt visible; all warps done with jt-1's compute

        if (jt + 2 < njt)
            prefetch(jt + 2, (jt + 2) % FNSTAGE);

        const float* Ks = sm + (jt % FNSTAGE) * FSTAGE;
        const float* Vs = Ks + 64 * KS_ST;

        // ---- S = Qhat @ K^T ----
        float S[8][4];
#pragma unroll
        for (int n = 0; n < 8; n++)
#pragma unroll
            for (int i = 0; i < 4; i++) S[n][i] = 0.f;

#pragma unroll
        for (int ks = 0; ks < 8; ks++) {
#pragma unroll
            for (int n = 0; n < 8; n++) {
                uint32_t kb[2];
                kb[0] = __float_as_uint(Ks[(n * 8 + g) * KS_ST + ks * 8 + tg]);
                kb[1] = __float_as_uint(Ks[(n * 8 + g) * KS_ST + ks * 8 + tg + 4]);
                mma_tf32(S[n], aq[ks], kb);
            }
        }

        // ---- causal mask ----
        if (jt >= 2 * qi) {
            const int r0 = qbase + w16 + g;
            const int r1 = r0 + 8;
            const int cb = jt * 64 + 2 * tg;
#pragma unroll
            for (int n = 0; n < 8; n++) {
                const int c0 = cb + n * 8;
                if (c0 > r0)     S[n][0] = -1e30f;
                if (c0 + 1 > r0) S[n][1] = -1e30f;
                if (c0 > r1)     S[n][2] = -1e30f;
                if (c0 + 1 > r1) S[n][3] = -1e30f;
            }
        }

        // ---- online softmax (base-2); P kept in S registers ----
        float rm0 = -1e30f, rm1 = -1e30f;
#pragma unroll
        for (int n = 0; n < 8; n++) {
            rm0 = fmaxf(rm0, fmaxf(S[n][0], S[n][1]));
            rm1 = fmaxf(rm1, fmaxf(S[n][2], S[n][3]));
        }
        rm0 = fmaxf(rm0, __shfl_xor_sync(0xffffffffu, rm0, 1));
        rm0 = fmaxf(rm0, __shfl_xor_sync(0xffffffffu, rm0, 2));
        rm1 = fmaxf(rm1, __shfl_xor_sync(0xffffffffu, rm1, 1));
        rm1 = fmaxf(rm1, __shfl_xor_sync(0xffffffffu, rm1, 2));

        const float mn0 = fmaxf(m0, rm0);
        const float mn1 = fmaxf(m1, rm1);
        const float corr0 = ex2(m0 - mn0);
        const float corr1 = ex2(m1 - mn1);
        m0 = mn0; m1 = mn1;

        float rs0 = 0.f, rs1 = 0.f;
#pragma unroll
        for (int n = 0; n < 8; n++) {
            float p0 = ex2(S[n][0] - mn0);
            float p1 = ex2(S[n][1] - mn0);
            float p2 = ex2(S[n][2] - mn1);
            float p3 = ex2(S[n][3] - mn1);
            rs0 += p0 + p1;
            rs1 += p2 + p3;
            O[n][0] *= corr0; O[n][1] *= corr0;
            O[n][2] *= corr1; O[n][3] *= corr1;
            S[n][0] = p0; S[n][1] = p1; S[n][2] = p2; S[n][3] = p3;
        }
        rs0 += __shfl_xor_sync(0xffffffffu, rs0, 1);
        rs0 += __shfl_xor_sync(0xffffffffu, rs0, 2);
        rs1 += __shfl_xor_sync(0xffffffffu, rs1, 1);
        rs1 += __shfl_xor_sync(0xffffffffu, rs1, 2);
        l0 = l0 * corr0 + rs0;
        l1 = l1 * corr1 + rs1;

        // ---- O += P @ V, P direct from registers (kv relabeled) ----
#pragma unroll
        for (int n = 0; n < 8; n++) {
            uint32_t pa[4];
            pa[0] = f2tf(S[n][0]);
            pa[1] = f2tf(S[n][2]);
            pa[2] = f2tf(S[n][1]);
            pa[3] = f2tf(S[n][3]);
#pragma unroll
            for (int nn = 0; nn < 8; nn++) {
                uint32_t vb[2];
                vb[0] = __float_as_uint(Vs[(n * 8 + 2 * tg) * VS_ST + nn * 8 + g]);
                vb[1] = __float_as_uint(Vs[(n * 8 + 2 * tg + 1) * VS_ST + nn * 8 + g]);
                mma_tf32(O[nn], pa, vb);
            }
        }
        // no trailing barrier: next tile's barrier protects stage reuse
    }

    const float inv0 = rcp(l0);
    const float inv1 = rcp(l1);
    const int r0 = qbase + w16 + g;
    float* yr0 = y + (size_t)b * SEQ * DOUT + (size_t)r0 * DOUT + hoff;
    float* yr1 = yr0 + 8 * DOUT;
#pragma unroll
    for (int n = 0; n < 8; n++) {
        const int c = n * 8 + 2 * tg;
        *(float2*)(yr0 + c) = make_float2(tf32r(O[n][0] * inv0), tf32r(O[n][1] * inv0));
        *(float2*)(yr1 + c) = make_float2(tf32r(O[n][2] * inv1), tf32r(O[n][3] * inv1));
    }
}

// ---------------------------------------------------------------------------
extern "C" void kernel_launch(void* const* d_in, const int* in_sizes, int n_in,
                              void* d_out, int out_size)
{
    const float* x     = (const float*)d_in[0];
    const float* w_qkv = (const float*)d_in[1];
    const float* w_out = (const float*)d_in[2];
    const float* b_out = (const float*)d_in[3];
    float* out = (float*)d_out;

    float *qkv_ptr, *y_ptr;
    cudaGetSymbolAddress((void**)&qkv_ptr, g_qkv);
    cudaGetSymbolAddress((void**)&y_ptr, g_y);

    cudaFuncSetAttribute(gemm_tf32_nt<false, true, true>,
                         cudaFuncAttributeMaxDynamicSharedMemorySize,
                         GEMM_SMEM_BYTES);
    cudaFuncSetAttribute(gemm_tf32_nt<true, false, false>,
                         cudaFuncAttributeMaxDynamicSharedMemorySize,
                         GEMM_SMEM_BYTES);
    cudaFuncSetAttribute(flash_mma_kernel,
                         cudaFuncAttributeMaxDynamicSharedMemorySize,
                         FLASH_SMEM_BYTES);

    // 1) QKV projection (output tf32-rounded, Q pre-scaled by 0.125*log2e)
    gemm_tf32_nt<false, true, true>
        <<<dim3(QKV_COLS / BN, M_ROWS / BM), 256, GEMM_SMEM_BYTES>>>(
        x, w_qkv, nullptr, qkv_ptr, M_ROWS, QKV_COLS, DIN);

    // 2) Flash attention (y stored tf32-rounded)
    flash_mma_kernel<<<dim3(SEQ / 128, BATCH * NHEAD), 256, FLASH_SMEM_BYTES>>>(
        qkv_ptr, y_ptr);

    // 3) Output projection + bias (final fp32 output)
    gemm_tf32_nt<true, false, false>
        <<<dim3(DOUT / BN, M_ROWS / BM), 256, GEMM_SMEM_BYTES>>>(
        y_ptr, w_out, b_out, out, M_ROWS, DOUT, DOUT);
}

// round 15
// speedup vs baseline: 1.2576x; 1.0155x over previous
#include <cuda_runtime.h>
#include <cuda_bf16.h>
#include <cstdint>

// Problem constants
#define BATCH 2
#define SEQ   2048
#define DIN   1024
#define DOUT  1024
#define NHEAD 16
#define HDIM  64
#define M_ROWS (BATCH * SEQ)          // 4096
#define QKV_COLS (3 * DOUT)           // 3072

// Scratch (device globals; no runtime allocation allowed)
__device__ float g_qkv[(size_t)M_ROWS * QKV_COLS];   // tf32-rounded, Q pre-scaled
__device__ float g_y[(size_t)M_ROWS * DOUT];         // tf32-rounded

// ---------------------------------------------------------------------------
// PTX helpers
// ---------------------------------------------------------------------------
__device__ __forceinline__ void cp_async16(void* smem, const void* gmem) {
    uint32_t s = (uint32_t)__cvta_generic_to_shared(smem);
    asm volatile("cp.async.cg.shared.global [%0], [%1], 16;\n" :: "r"(s), "l"(gmem));
}
__device__ __forceinline__ void cp_commit() {
    asm volatile("cp.async.commit_group;\n");
}
template <int N>
__device__ __forceinline__ void cp_wait() {
    asm volatile("cp.async.wait_group %0;\n" :: "n"(N));
}
__device__ __forceinline__ uint32_t f2tf(float f) {
    uint32_t r;
    asm("cvt.rna.tf32.f32 %0, %1;" : "=r"(r) : "f"(f));
    return r;
}
__device__ __forceinline__ float tf32r(float f) {
    return __uint_as_float(f2tf(f));
}
__device__ __forceinline__ float ex2(float x) {
    float y;
    asm("ex2.approx.f32 %0, %1;" : "=f"(y) : "f"(x));
    return y;
}
__device__ __forceinline__ float rcp(float x) {
    float y;
    asm("rcp.approx.f32 %0, %1;" : "=f"(y) : "f"(x));
    return y;
}
__device__ __forceinline__ void mma_tf32(float c[4],
                                         const uint32_t a[4],
                                         const uint32_t b[2]) {
    asm volatile(
        "mma.sync.aligned.m16n8k8.row.col.f32.tf32.tf32.f32 "
        "{%0,%1,%2,%3}, {%4,%5,%6,%7}, {%8,%9}, {%0,%1,%2,%3};\n"
        : "+f"(c[0]), "+f"(c[1]), "+f"(c[2]), "+f"(c[3])
        : "r"(a[0]), "r"(a[1]), "r"(a[2]), "r"(a[3]), "r"(b[0]), "r"(b[1]));
}

// ---------------------------------------------------------------------------
// TF32 tensor-core GEMM: C[M,N] = A[M,K] @ B[N,K]^T (+bias)
// R7/R11/R13/R14 EXACT (measured best ~197us).
// ---------------------------------------------------------------------------
#define BM 128
#define BN 128
#define BK 16
#define GST 20                       // BK + 4 pad
#define STAGE_FLOATS (2 * BM * GST)  // 5120 floats
#define NSTAGE 3
#define GEMM_SMEM_BYTES (NSTAGE * STAGE_FLOATS * 4)   // 61440 B

template <bool BIAS, bool ROUND, bool QSCALE>
__global__ __launch_bounds__(256, 2) void gemm_tf32_nt(
    const float* __restrict__ A, const float* __restrict__ B,
    const float* __restrict__ bias, float* __restrict__ C,
    int M, int N, int K)
{
    extern __shared__ float sm[];

    const int tid  = threadIdx.x;
    const int lane = tid & 31;
    const int warp = tid >> 5;
    const int wm = warp & 1;          // 2 warps along M (64 rows each)
    const int wn = warp >> 1;         // 4 warps along N (32 cols each)
    const int g  = lane >> 2;
    const int tg = lane & 3;

    const int bm = blockIdx.y * BM;
    const int bn = blockIdx.x * BN;

    const int ldr = tid >> 2;          // 0..63
    const int ldc = (tid & 3) * 4;     // 0,4,8,12

    const float* Ag0 = A + (size_t)(bm + ldr) * K + ldc;
    const float* Ag1 = A + (size_t)(bm + ldr + 64) * K + ldc;
    const float* Bg0 = B + (size_t)(bn + ldr) * K + ldc;
    const float* Bg1 = B + (size_t)(bn + ldr + 64) * K + ldc;

    auto load_stage = [&](int s, int ko) {
        float* As = sm + s * STAGE_FLOATS;
        float* Bs = As + BM * GST;
        cp_async16(As + ldr * GST + ldc,        Ag0 + ko);
        cp_async16(As + (ldr + 64) * GST + ldc, Ag1 + ko);
        cp_async16(Bs + ldr * GST + ldc,        Bg0 + ko);
        cp_async16(Bs + (ldr + 64) * GST + ldc, Bg1 + ko);
        cp_commit();
    };

    float acc[4][4][4];
#pragma unroll
    for (int mt = 0; mt < 4; mt++)
#pragma unroll
        for (int nt = 0; nt < 4; nt++)
#pragma unroll
            for (int i = 0; i < 4; i++) acc[mt][nt][i] = 0.f;

    const int nstages = K / BK;

    load_stage(0, 0);
    load_stage(1, BK);

    for (int it = 0; it < nstages; it++) {
        if (it + 1 < nstages) cp_wait<1>();
        else                  cp_wait<0>();
        __syncthreads();

        if (it + 2 < nstages)
            load_stage((it + 2) % NSTAGE, (it + 2) * BK);

        const float* Ab = sm + (it % NSTAGE) * STAGE_FLOATS;
        const float* Bb = Ab + BM * GST;

#pragma unroll
        for (int ks = 0; ks < BK; ks += 8) {
            uint32_t af[4][4], bf[4][2];
#pragma unroll
            for (int mt = 0; mt < 4; mt++) {
                const int m = wm * 64 + mt * 16;
                af[mt][0] = f2tf(Ab[(m + g) * GST + ks + tg]);
                af[mt][1] = f2tf(Ab[(m + g + 8) * GST + ks + tg]);
                af[mt][2] = f2tf(Ab[(m + g) * GST + ks + tg + 4]);
                af[mt][3] = f2tf(Ab[(m + g + 8) * GST + ks + tg + 4]);
            }
#pragma unroll
            for (int nt = 0; nt < 4; nt++) {
                const int n = wn * 32 + nt * 8;
                bf[nt][0] = f2tf(Bb[(n + g) * GST + ks + tg]);
                bf[nt][1] = f2tf(Bb[(n + g) * GST + ks + tg + 4]);
            }
#pragma unroll
            for (int mt = 0; mt < 4; mt++)
#pragma unroll
                for (int nt = 0; nt < 4; nt++)
                    mma_tf32(acc[mt][nt], af[mt], bf[nt]);
        }
    }

    const float qsc = 0.125f * 1.4426950408889634f;

#pragma unroll
    for (int mt = 0; mt < 4; mt++) {
        const int row0 = bm + wm * 64 + mt * 16 + g;
#pragma unroll
        for (int nt = 0; nt < 4; nt++) {
            const int col = bn + wn * 32 + nt * 8 + 2 * tg;
            float v0 = acc[mt][nt][0], v1 = acc[mt][nt][1];
            float v2 = acc[mt][nt][2], v3 = acc[mt][nt][3];
            if (QSCALE && col < DOUT) { v0 *= qsc; v1 *= qsc; v2 *= qsc; v3 *= qsc; }
            if (BIAS) {
                float b0 = bias[col], b1 = bias[col + 1];
                v0 += b0; v1 += b1; v2 += b0; v3 += b1;
            }
            if (ROUND) {
                v0 = tf32r(v0); v1 = tf32r(v1);
                v2 = tf32r(v2); v3 = tf32r(v3);
            }
            *(float2*)(C + (size_t)row0 * N + col) = make_float2(v0, v1);
            *(float2*)(C + (size_t)(row0 + 8) * N + col) = make_float2(v2, v3);
        }
    }
}

// ---------------------------------------------------------------------------
// Flash attention (causal), tf32 mma, register-direct P@V.
// NEW: 128-wide kv tiles — one softmax pass / shuffle-reduce / barrier per
// 128 kv columns (was per 64). 3 K/V stages (204KB smem, 1 CTA/SM); the
// one-shot Q staging overlaps stage-0 memory (dead after aq regs built).
// ---------------------------------------------------------------------------
#define KS_ST 68
#define VS_ST 68
#define FSTAGE (128 * KS_ST + 128 * VS_ST)   // floats per stage (K+V)
#define FNSTAGE 3
#define FLASH_SMEM_BYTES (FNSTAGE * FSTAGE * 4)   // 208896 B

__global__ __launch_bounds__(256, 1) void flash_mma_kernel(
    const float* __restrict__ qkv, float* __restrict__ y)
{
    extern __shared__ float sm[];

    const int qi = (int)gridDim.x - 1 - (int)blockIdx.x;  // heavy tiles first
    const int bh = blockIdx.y;
    const int b  = bh >> 4;
    const int h  = bh & 15;
    const int qbase = qi * 128;

    const float* base = qkv + (size_t)b * SEQ * QKV_COLS;
    const int hoff = h * HDIM;

    const int tid  = threadIdx.x;
    const int lane = tid & 31;
    const int warp = tid >> 5;
    const int g  = lane >> 2;
    const int tg = lane & 3;
    const int w16 = warp * 16;

    // --- stage Q into stage-0 region (reused by K/V after aq is built) ---
    float (*Qs)[68] = (float(*)[68])sm;
    for (int i = tid; i < 128 * 16; i += 256) {
        int r  = i >> 4;
        int c4 = (i & 15) * 4;
        float4 v = *(const float4*)(base + (size_t)(qbase + r) * QKV_COLS + hoff + c4);
        *(float4*)&Qs[r][c4] = v;
    }
    __syncthreads();

    uint32_t aq[8][4];
#pragma unroll
    for (int ks = 0; ks < 8; ks++) {
        aq[ks][0] = __float_as_uint(Qs[w16 + g][ks * 8 + tg]);
        aq[ks][1] = __float_as_uint(Qs[w16 + g + 8][ks * 8 + tg]);
        aq[ks][2] = __float_as_uint(Qs[w16 + g][ks * 8 + tg + 4]);
        aq[ks][3] = __float_as_uint(Qs[w16 + g + 8][ks * 8 + tg + 4]);
    }
    __syncthreads();   // Q region dead; safe for K/V prefetch to overwrite

    float O[8][4];
#pragma unroll
    for (int n = 0; n < 8; n++)
#pragma unroll
        for (int i = 0; i < 4; i++) O[n][i] = 0.f;
    float m0 = -1e30f, m1 = -1e30f, l0 = 0.f, l1 = 0.f;

    const int njt = qi + 1;   // 128-wide kv tiles

    auto prefetch = [&](int jt, int stage) {
        const int jb = jt * 128;
        float* Ks = sm + stage * FSTAGE;
        float* Vs = Ks + 128 * KS_ST;
        for (int i = tid; i < 128 * 16; i += 256) {
            int r  = i >> 4;
            int c4 = (i & 15) * 4;
            const float* rowp = base + (size_t)(jb + r) * QKV_COLS + hoff;
            cp_async16(Ks + r * KS_ST + c4, rowp + DOUT + c4);
            cp_async16(Vs + r * VS_ST + c4, rowp + 2 * DOUT + c4);
        }
        cp_commit();
    };

    prefetch(0, 0);
    if (njt > 1) prefetch(1, 1);

    for (int jt = 0; jt < njt; jt++) {
        if (jt + 1 < njt) cp_wait<1>();
        else              cp_wait<0>();
        __syncthreads();   // stage jt visible; all warps done with jt-1

        if (jt + 2 < njt)
            prefetch(jt + 2, (jt + 2) % FNSTAGE);

        const float* Ks = sm + (jt % FNSTAGE) * FSTAGE;
        const float* Vs = Ks + 128 * KS_ST;

        // ---- S = Qhat @ K^T  (16x128 per warp) ----
        float S[16][4];
#pragma unroll
        for (int n = 0; n < 16; n++)
#pragma unroll
            for (int i = 0; i < 4; i++) S[n][i] = 0.f;

#pragma unroll
        for (int ks = 0; ks < 8; ks++) {
#pragma unroll
            for (int n = 0; n < 16; n++) {
                uint32_t kb[2];
                kb[0] = __float_as_uint(Ks[(n * 8 + g) * KS_ST + ks * 8 + tg]);
                kb[1] = __float_as_uint(Ks[(n * 8 + g) * KS_ST + ks * 8 + tg + 4]);
                mma_tf32(S[n], aq[ks], kb);
            }
        }

        // ---- causal mask (diagonal tile only) ----
        if (jt == qi) {
            const int r0 = qbase + w16 + g;
            const int r1 = r0 + 8;
            const int cb = jt * 128 + 2 * tg;
#pragma unroll
            for (int n = 0; n < 16; n++) {
                const int c0 = cb + n * 8;
                if (c0 > r0)     S[n][0] = -1e30f;
                if (c0 + 1 > r0) S[n][1] = -1e30f;
                if (c0 > r1)     S[n][2] = -1e30f;
                if (c0 + 1 > r1) S[n][3] = -1e30f;
            }
        }

        // ---- online softmax (base-2); one pass per 128 kv cols ----
        float rm0 = -1e30f, rm1 = -1e30f;
#pragma unroll
        for (int n = 0; n < 16; n++) {
            rm0 = fmaxf(rm0, fmaxf(S[n][0], S[n][1]));
            rm1 = fmaxf(rm1, fmaxf(S[n][2], S[n][3]));
        }
        rm0 = fmaxf(rm0, __shfl_xor_sync(0xffffffffu, rm0, 1));
        rm0 = fmaxf(rm0, __shfl_xor_sync(0xffffffffu, rm0, 2));
        rm1 = fmaxf(rm1, __shfl_xor_sync(0xffffffffu, rm1, 1));
        rm1 = fmaxf(rm1, __shfl_xor_sync(0xffffffffu, rm1, 2));

        const float mn0 = fmaxf(m0, rm0);
        const float mn1 = fmaxf(m1, rm1);
        const float corr0 = ex2(m0 - mn0);
        const float corr1 = ex2(m1 - mn1);
        m0 = mn0; m1 = mn1;

        float rs0 = 0.f, rs1 = 0.f;
#pragma unroll
        for (int n = 0; n < 16; n++) {
            float p0 = ex2(S[n][0] - mn0);
            float p1 = ex2(S[n][1] - mn0);
            float p2 = ex2(S[n][2] - mn1);
            float p3 = ex2(S[n][3] - mn1);
            rs0 += p0 + p1;
            rs1 += p2 + p3;
            S[n][0] = p0; S[n][1] = p1; S[n][2] = p2; S[n][3] = p3;
        }
#pragma unroll
        for (int n = 0; n < 8; n++) {
            O[n][0] *= corr0; O[n][1] *= corr0;
            O[n][2] *= corr1; O[n][3] *= corr1;
        }
        rs0 += __shfl_xor_sync(0xffffffffu, rs0, 1);
        rs0 += __shfl_xor_sync(0xffffffffu, rs0, 2);
        rs1 += __shfl_xor_sync(0xffffffffu, rs1, 1);
        rs1 += __shfl_xor_sync(0xffffffffu, rs1, 2);
        l0 = l0 * corr0 + rs0;
        l1 = l1 * corr1 + rs1;

        // ---- O += P @ V, P direct from registers (kv relabeled) ----
#pragma unroll
        for (int n = 0; n < 16; n++) {
            uint32_t pa[4];
            pa[0] = f2tf(S[n][0]);
            pa[1] = f2tf(S[n][2]);
            pa[2] = f2tf(S[n][1]);
            pa[3] = f2tf(S[n][3]);
#pragma unroll
            for (int nn = 0; nn < 8; nn++) {
                uint32_t vb[2];
                vb[0] = __float_as_uint(Vs[(n * 8 + 2 * tg) * VS_ST + nn * 8 + g]);
                vb[1] = __float_as_uint(Vs[(n * 8 + 2 * tg + 1) * VS_ST + nn * 8 + g]);
                mma_tf32(O[nn], pa, vb);
            }
        }
        // no trailing barrier: next tile's barrier protects stage reuse
    }

    const float inv0 = rcp(l0);
    const float inv1 = rcp(l1);
    const int r0 = qbase + w16 + g;
    float* yr0 = y + (size_t)b * SEQ * DOUT + (size_t)r0 * DOUT + hoff;
    float* yr1 = yr0 + 8 * DOUT;
#pragma unroll
    for (int n = 0; n < 8; n++) {
        const int c = n * 8 + 2 * tg;
        *(float2*)(yr0 + c) = make_float2(tf32r(O[n][0] * inv0), tf32r(O[n][1] * inv0));
        *(float2*)(yr1 + c) = make_float2(tf32r(O[n][2] * inv1), tf32r(O[n][3] * inv1));
    }
}

// ---------------------------------------------------------------------------
extern "C" void kernel_launch(void* const* d_in, const int* in_sizes, int n_in,
                              void* d_out, int out_size)
{
    const float* x     = (const float*)d_in[0];
    const float* w_qkv = (const float*)d_in[1];
    const float* w_out = (const float*)d_in[2];
    const float* b_out = (const float*)d_in[3];
    float* out = (float*)d_out;

    float *qkv_ptr, *y_ptr;
    cudaGetSymbolAddress((void**)&qkv_ptr, g_qkv);
    cudaGetSymbolAddress((void**)&y_ptr, g_y);

    cudaFuncSetAttribute(gemm_tf32_nt<false, true, true>,
                         cudaFuncAttributeMaxDynamicSharedMemorySize,
                         GEMM_SMEM_BYTES);
    cudaFuncSetAttribute(gemm_tf32_nt<true, false, false>,
                         cudaFuncAttributeMaxDynamicSharedMemorySize,
                         GEMM_SMEM_BYTES);
    cudaFuncSetAttribute(flash_mma_kernel,
                         cudaFuncAttributeMaxDynamicSharedMemorySize,
                         FLASH_SMEM_BYTES);

    // 1) QKV projection (output tf32-rounded, Q pre-scaled by 0.125*log2e)
    gemm_tf32_nt<false, true, true>
        <<<dim3(QKV_COLS / BN, M_ROWS / BM), 256, GEMM_SMEM_BYTES>>>(
        x, w_qkv, nullptr, qkv_ptr, M_ROWS, QKV_COLS, DIN);

    // 2) Flash attention (y stored tf32-rounded)
    flash_mma_kernel<<<dim3(SEQ / 128, BATCH * NHEAD), 256, FLASH_SMEM_BYTES>>>(
        qkv_ptr, y_ptr);

    // 3) Output projection + bias (final fp32 output)
    gemm_tf32_nt<true, false, false>
        <<<dim3(DOUT / BN, M_ROWS / BM), 256, GEMM_SMEM_BYTES>>>(
        y_ptr, w_out, b_out, out, M_ROWS, DOUT, DOUT);
}

// round 16
// speedup vs baseline: 1.2699x; 1.0098x over previous
#include <cuda_runtime.h>
#include <cuda_bf16.h>
#include <cstdint>

// Problem constants
#define BATCH 2
#define SEQ   2048
#define DIN   1024
#define DOUT  1024
#define NHEAD 16
#define HDIM  64
#define M_ROWS (BATCH * SEQ)          // 4096
#define QKV_COLS (3 * DOUT)           // 3072

// Scratch (device globals; no runtime allocation allowed)
__device__ float g_qkv[(size_t)M_ROWS * QKV_COLS];   // tf32-rounded, Q pre-scaled
__device__ float g_y[(size_t)M_ROWS * DOUT];         // tf32-rounded

// ---------------------------------------------------------------------------
// PTX helpers
// ---------------------------------------------------------------------------
__device__ __forceinline__ void cp_async16(void* smem, const void* gmem) {
    uint32_t s = (uint32_t)__cvta_generic_to_shared(smem);
    asm volatile("cp.async.cg.shared.global [%0], [%1], 16;\n" :: "r"(s), "l"(gmem));
}
__device__ __forceinline__ void cp_commit() {
    asm volatile("cp.async.commit_group;\n");
}
template <int N>
__device__ __forceinline__ void cp_wait() {
    asm volatile("cp.async.wait_group %0;\n" :: "n"(N));
}
__device__ __forceinline__ uint32_t f2tf(float f) {
    uint32_t r;
    asm("cvt.rna.tf32.f32 %0, %1;" : "=r"(r) : "f"(f));
    return r;
}
__device__ __forceinline__ float tf32r(float f) {
    return __uint_as_float(f2tf(f));
}
__device__ __forceinline__ float ex2(float x) {
    float y;
    asm("ex2.approx.f32 %0, %1;" : "=f"(y) : "f"(x));
    return y;
}
__device__ __forceinline__ float rcp(float x) {
    float y;
    asm("rcp.approx.f32 %0, %1;" : "=f"(y) : "f"(x));
    return y;
}
__device__ __forceinline__ void mma_tf32(float c[4],
                                         const uint32_t a[4],
                                         const uint32_t b[2]) {
    asm volatile(
        "mma.sync.aligned.m16n8k8.row.col.f32.tf32.tf32.f32 "
        "{%0,%1,%2,%3}, {%4,%5,%6,%7}, {%8,%9}, {%0,%1,%2,%3};\n"
        : "+f"(c[0]), "+f"(c[1]), "+f"(c[2]), "+f"(c[3])
        : "r"(a[0]), "r"(a[1]), "r"(a[2]), "r"(a[3]), "r"(b[0]), "r"(b[1]));
}

// ---------------------------------------------------------------------------
// TF32 tensor-core GEMM: C[M,N] = A[M,K] @ B[N,K]^T (+bias)
// R7/R11/R13/R14/R15 EXACT (measured best ~197us).
// ---------------------------------------------------------------------------
#define BM 128
#define BN 128
#define BK 16
#define GST 20                       // BK + 4 pad
#define STAGE_FLOATS (2 * BM * GST)  // 5120 floats
#define NSTAGE 3
#define GEMM_SMEM_BYTES (NSTAGE * STAGE_FLOATS * 4)   // 61440 B

template <bool BIAS, bool ROUND, bool QSCALE>
__global__ __launch_bounds__(256, 2) void gemm_tf32_nt(
    const float* __restrict__ A, const float* __restrict__ B,
    const float* __restrict__ bias, float* __restrict__ C,
    int M, int N, int K)
{
    extern __shared__ float sm[];

    const int tid  = threadIdx.x;
    const int lane = tid & 31;
    const int warp = tid >> 5;
    const int wm = warp & 1;          // 2 warps along M (64 rows each)
    const int wn = warp >> 1;         // 4 warps along N (32 cols each)
    const int g  = lane >> 2;
    const int tg = lane & 3;

    const int bm = blockIdx.y * BM;
    const int bn = blockIdx.x * BN;

    const int ldr = tid >> 2;          // 0..63
    const int ldc = (tid & 3) * 4;     // 0,4,8,12

    const float* Ag0 = A + (size_t)(bm + ldr) * K + ldc;
    const float* Ag1 = A + (size_t)(bm + ldr + 64) * K + ldc;
    const float* Bg0 = B + (size_t)(bn + ldr) * K + ldc;
    const float* Bg1 = B + (size_t)(bn + ldr + 64) * K + ldc;

    auto load_stage = [&](int s, int ko) {
        float* As = sm + s * STAGE_FLOATS;
        float* Bs = As + BM * GST;
        cp_async16(As + ldr * GST + ldc,        Ag0 + ko);
        cp_async16(As + (ldr + 64) * GST + ldc, Ag1 + ko);
        cp_async16(Bs + ldr * GST + ldc,        Bg0 + ko);
        cp_async16(Bs + (ldr + 64) * GST + ldc, Bg1 + ko);
        cp_commit();
    };

    float acc[4][4][4];
#pragma unroll
    for (int mt = 0; mt < 4; mt++)
#pragma unroll
        for (int nt = 0; nt < 4; nt++)
#pragma unroll
            for (int i = 0; i < 4; i++) acc[mt][nt][i] = 0.f;

    const int nstages = K / BK;

    load_stage(0, 0);
    load_stage(1, BK);

    for (int it = 0; it < nstages; it++) {
        if (it + 1 < nstages) cp_wait<1>();
        else                  cp_wait<0>();
        __syncthreads();

        if (it + 2 < nstages)
            load_stage((it + 2) % NSTAGE, (it + 2) * BK);

        const float* Ab = sm + (it % NSTAGE) * STAGE_FLOATS;
        const float* Bb = Ab + BM * GST;

#pragma unroll
        for (int ks = 0; ks < BK; ks += 8) {
            uint32_t af[4][4], bf[4][2];
#pragma unroll
            for (int mt = 0; mt < 4; mt++) {
                const int m = wm * 64 + mt * 16;
                af[mt][0] = f2tf(Ab[(m + g) * GST + ks + tg]);
                af[mt][1] = f2tf(Ab[(m + g + 8) * GST + ks + tg]);
                af[mt][2] = f2tf(Ab[(m + g) * GST + ks + tg + 4]);
                af[mt][3] = f2tf(Ab[(m + g + 8) * GST + ks + tg + 4]);
            }
#pragma unroll
            for (int nt = 0; nt < 4; nt++) {
                const int n = wn * 32 + nt * 8;
                bf[nt][0] = f2tf(Bb[(n + g) * GST + ks + tg]);
                bf[nt][1] = f2tf(Bb[(n + g) * GST + ks + tg + 4]);
            }
#pragma unroll
            for (int mt = 0; mt < 4; mt++)
#pragma unroll
                for (int nt = 0; nt < 4; nt++)
                    mma_tf32(acc[mt][nt], af[mt], bf[nt]);
        }
    }

    const float qsc = 0.125f * 1.4426950408889634f;

#pragma unroll
    for (int mt = 0; mt < 4; mt++) {
        const int row0 = bm + wm * 64 + mt * 16 + g;
#pragma unroll
        for (int nt = 0; nt < 4; nt++) {
            const int col = bn + wn * 32 + nt * 8 + 2 * tg;
            float v0 = acc[mt][nt][0], v1 = acc[mt][nt][1];
            float v2 = acc[mt][nt][2], v3 = acc[mt][nt][3];
            if (QSCALE && col < DOUT) { v0 *= qsc; v1 *= qsc; v2 *= qsc; v3 *= qsc; }
            if (BIAS) {
                float b0 = bias[col], b1 = bias[col + 1];
                v0 += b0; v1 += b1; v2 += b0; v3 += b1;
            }
            if (ROUND) {
                v0 = tf32r(v0); v1 = tf32r(v1);
                v2 = tf32r(v2); v3 = tf32r(v3);
            }
            *(float2*)(C + (size_t)row0 * N + col) = make_float2(v0, v1);
            *(float2*)(C + (size_t)(row0 + 8) * N + col) = make_float2(v2, v3);
        }
    }
}

// ---------------------------------------------------------------------------
// Flash attention (causal), tf32 mma, register-direct P@V, 128-wide kv tiles.
// NEW: d-relabeled S-GEMM fragments -> K fragment loads are LDS.128
// (256 LDS.32 -> 64 LDS.128 per warp-tile). mma k-group 2j covers
// d=16j+{4tg,4tg+1}, group 2j+1 covers d=16j+{4tg+2,4tg+3}; Q A-fragments
// built with the same relabel (one-shot). KS_ST=80 (20 blocks/row, 20%8==4)
// makes the LDS.128 pattern provably conflict-free. V unchanged (stride 68).
// SMEM: 3 stages x (128*80 + 128*68) floats = 227328 B, 1 CTA/SM.
// ---------------------------------------------------------------------------
#define KS_ST 80
#define VS_ST 68
#define FSTAGE (128 * KS_ST + 128 * VS_ST)   // floats per stage (K+V)
#define FNSTAGE 3
#define FLASH_SMEM_BYTES (FNSTAGE * FSTAGE * 4)   // 227328 B

__global__ __launch_bounds__(256, 1) void flash_mma_kernel(
    const float* __restrict__ qkv, float* __restrict__ y)
{
    extern __shared__ float sm[];

    const int qi = (int)gridDim.x - 1 - (int)blockIdx.x;  // heavy tiles first
    const int bh = blockIdx.y;
    const int b  = bh >> 4;
    const int h  = bh & 15;
    const int qbase = qi * 128;

    const float* base = qkv + (size_t)b * SEQ * QKV_COLS;
    const int hoff = h * HDIM;

    const int tid  = threadIdx.x;
    const int lane = tid & 31;
    const int warp = tid >> 5;
    const int g  = lane >> 2;
    const int tg = lane & 3;
    const int w16 = warp * 16;

    // --- stage Q into stage-0 K region (dead after aq regs built) ---
    float (*Qs)[KS_ST] = (float(*)[KS_ST])sm;
    for (int i = tid; i < 128 * 16; i += 256) {
        int r  = i >> 4;
        int c4 = (i & 15) * 4;
        float4 v = *(const float4*)(base + (size_t)(qbase + r) * QKV_COLS + hoff + c4);
        *(float4*)&Qs[r][c4] = v;
    }
    __syncthreads();

    // A-fragments with d-relabel: group 2j k-slot tg -> d=16j+4tg,
    // slot tg+4 -> d=16j+4tg+1; group 2j+1 -> +2,+3.
    uint32_t aq[8][4];
#pragma unroll
    for (int j = 0; j < 4; j++) {
        float4 q0 = *(const float4*)&Qs[w16 + g][16 * j + 4 * tg];
        float4 q1 = *(const float4*)&Qs[w16 + g + 8][16 * j + 4 * tg];
        aq[2 * j][0] = __float_as_uint(q0.x);
        aq[2 * j][1] = __float_as_uint(q1.x);
        aq[2 * j][2] = __float_as_uint(q0.y);
        aq[2 * j][3] = __float_as_uint(q1.y);
        aq[2 * j + 1][0] = __float_as_uint(q0.z);
        aq[2 * j + 1][1] = __float_as_uint(q1.z);
        aq[2 * j + 1][2] = __float_as_uint(q0.w);
        aq[2 * j + 1][3] = __float_as_uint(q1.w);
    }
    __syncthreads();   // Q region dead; safe for K/V prefetch to overwrite

    float O[8][4];
#pragma unroll
    for (int n = 0; n < 8; n++)
#pragma unroll
        for (int i = 0; i < 4; i++) O[n][i] = 0.f;
    float m0 = -1e30f, m1 = -1e30f, l0 = 0.f, l1 = 0.f;

    const int njt = qi + 1;   // 128-wide kv tiles

    auto prefetch = [&](int jt, int stage) {
        const int jb = jt * 128;
        float* Ks = sm + stage * FSTAGE;
        float* Vs = Ks + 128 * KS_ST;
        for (int i = tid; i < 128 * 16; i += 256) {
            int r  = i >> 4;
            int c4 = (i & 15) * 4;
            const float* rowp = base + (size_t)(jb + r) * QKV_COLS + hoff;
            cp_async16(Ks + r * KS_ST + c4, rowp + DOUT + c4);
            cp_async16(Vs + r * VS_ST + c4, rowp + 2 * DOUT + c4);
        }
        cp_commit();
    };

    prefetch(0, 0);
    if (njt > 1) prefetch(1, 1);

    for (int jt = 0; jt < njt; jt++) {
        if (jt + 1 < njt) cp_wait<1>();
        else              cp_wait<0>();
        __syncthreads();   // stage jt visible; all warps done with jt-1

        if (jt + 2 < njt)
            prefetch(jt + 2, (jt + 2) % FNSTAGE);

        const float* Ks = sm + (jt % FNSTAGE) * FSTAGE;
        const float* Vs = Ks + 128 * KS_ST;

        // ---- S = Qhat @ K^T  (16x128 per warp), vectorized K loads ----
        float S[16][4];
#pragma unroll
        for (int n = 0; n < 16; n++)
#pragma unroll
            for (int i = 0; i < 4; i++) S[n][i] = 0.f;

#pragma unroll
        for (int j = 0; j < 4; j++) {
#pragma unroll
            for (int n = 0; n < 16; n++) {
                float4 kf = *(const float4*)&Ks[(n * 8 + g) * KS_ST + 16 * j + 4 * tg];
                uint32_t kb0[2] = {__float_as_uint(kf.x), __float_as_uint(kf.y)};
                uint32_t kb1[2] = {__float_as_uint(kf.z), __float_as_uint(kf.w)};
                mma_tf32(S[n], aq[2 * j], kb0);
                mma_tf32(S[n], aq[2 * j + 1], kb1);
            }
        }

        // ---- causal mask (diagonal tile only) ----
        if (jt == qi) {
            const int r0 = qbase + w16 + g;
            const int r1 = r0 + 8;
            const int cb = jt * 128 + 2 * tg;
#pragma unroll
            for (int n = 0; n < 16; n++) {
                const int c0 = cb + n * 8;
                if (c0 > r0)     S[n][0] = -1e30f;
                if (c0 + 1 > r0) S[n][1] = -1e30f;
                if (c0 > r1)     S[n][2] = -1e30f;
                if (c0 + 1 > r1) S[n][3] = -1e30f;
            }
        }

        // ---- online softmax (base-2); one pass per 128 kv cols ----
        float rm0 = -1e30f, rm1 = -1e30f;
#pragma unroll
        for (int n = 0; n < 16; n++) {
            rm0 = fmaxf(rm0, fmaxf(S[n][0], S[n][1]));
            rm1 = fmaxf(rm1, fmaxf(S[n][2], S[n][3]));
        }
        rm0 = fmaxf(rm0, __shfl_xor_sync(0xffffffffu, rm0, 1));
        rm0 = fmaxf(rm0, __shfl_xor_sync(0xffffffffu, rm0, 2));
        rm1 = fmaxf(rm1, __shfl_xor_sync(0xffffffffu, rm1, 1));
        rm1 = fmaxf(rm1, __shfl_xor_sync(0xffffffffu, rm1, 2));

        const float mn0 = fmaxf(m0, rm0);
        const float mn1 = fmaxf(m1, rm1);
        const float corr0 = ex2(m0 - mn0);
        const float corr1 = ex2(m1 - mn1);
        m0 = mn0; m1 = mn1;

        float rs0 = 0.f, rs1 = 0.f;
#pragma unroll
        for (int n = 0; n < 16; n++) {
            float p0 = ex2(S[n][0] - mn0);
            float p1 = ex2(S[n][1] - mn0);
            float p2 = ex2(S[n][2] - mn1);
            float p3 = ex2(S[n][3] - mn1);
            rs0 += p0 + p1;
            rs1 += p2 + p3;
            S[n][0] = p0; S[n][1] = p1; S[n][2] = p2; S[n][3] = p3;
        }
#pragma unroll
        for (int n = 0; n < 8; n++) {
            O[n][0] *= corr0; O[n][1] *= corr0;
            O[n][2] *= corr1; O[n][3] *= corr1;
        }
        rs0 += __shfl_xor_sync(0xffffffffu, rs0, 1);
        rs0 += __shfl_xor_sync(0xffffffffu, rs0, 2);
        rs1 += __shfl_xor_sync(0xffffffffu, rs1, 1);
        rs1 += __shfl_xor_sync(0xffffffffu, rs1, 2);
        l0 = l0 * corr0 + rs0;
        l1 = l1 * corr1 + rs1;

        // ---- O += P @ V, P direct from registers (kv relabeled) ----
#pragma unroll
        for (int n = 0; n < 16; n++) {
            uint32_t pa[4];
            pa[0] = f2tf(S[n][0]);
            pa[1] = f2tf(S[n][2]);
            pa[2] = f2tf(S[n][1]);
            pa[3] = f2tf(S[n][3]);
#pragma unroll
            for (int nn = 0; nn < 8; nn++) {
                uint32_t vb[2];
                vb[0] = __float_as_uint(Vs[(n * 8 + 2 * tg) * VS_ST + nn * 8 + g]);
                vb[1] = __float_as_uint(Vs[(n * 8 + 2 * tg + 1) * VS_ST + nn * 8 + g]);
                mma_tf32(O[nn], pa, vb);
            }
        }
        // no trailing barrier: next tile's barrier protects stage reuse
    }

    const float inv0 = rcp(l0);
    const float inv1 = rcp(l1);
    const int r0 = qbase + w16 + g;
    float* yr0 = y + (size_t)b * SEQ * DOUT + (size_t)r0 * DOUT + hoff;
    float* yr1 = yr0 + 8 * DOUT;
#pragma unroll
    for (int n = 0; n < 8; n++) {
        const int c = n * 8 + 2 * tg;
        *(float2*)(yr0 + c) = make_float2(tf32r(O[n][0] * inv0), tf32r(O[n][1] * inv0));
        *(float2*)(yr1 + c) = make_float2(tf32r(O[n][2] * inv1), tf32r(O[n][3] * inv1));
    }
}

// ---------------------------------------------------------------------------
extern "C" void kernel_launch(void* const* d_in, const int* in_sizes, int n_in,
                              void* d_out, int out_size)
{
    const float* x     = (const float*)d_in[0];
    const float* w_qkv = (const float*)d_in[1];
    const float* w_out = (const float*)d_in[2];
    const float* b_out = (const float*)d_in[3];
    float* out = (float*)d_out;

    float *qkv_ptr, *y_ptr;
    cudaGetSymbolAddress((void**)&qkv_ptr, g_qkv);
    cudaGetSymbolAddress((void**)&y_ptr, g_y);

    cudaFuncSetAttribute(gemm_tf32_nt<false, true, true>,
                         cudaFuncAttributeMaxDynamicSharedMemorySize,
                         GEMM_SMEM_BYTES);
    cudaFuncSetAttribute(gemm_tf32_nt<true, false, false>,
                         cudaFuncAttributeMaxDynamicSharedMemorySize,
                         GEMM_SMEM_BYTES);
    cudaFuncSetAttribute(flash_mma_kernel,
                         cudaFuncAttributeMaxDynamicSharedMemorySize,
                         FLASH_SMEM_BYTES);

    // 1) QKV projection (output tf32-rounded, Q pre-scaled by 0.125*log2e)
    gemm_tf32_nt<false, true, true>
        <<<dim3(QKV_COLS / BN, M_ROWS / BM), 256, GEMM_SMEM_BYTES>>>(
        x, w_qkv, nullptr, qkv_ptr, M_ROWS, QKV_COLS, DIN);

    // 2) Flash attention (y stored tf32-rounded)
    flash_mma_kernel<<<dim3(SEQ / 128, BATCH * NHEAD), 256, FLASH_SMEM_BYTES>>>(
        qkv_ptr, y_ptr);

    // 3) Output projection + bias (final fp32 output)
    gemm_tf32_nt<true, false, false>
        <<<dim3(DOUT / BN, M_ROWS / BM), 256, GEMM_SMEM_BYTES>>>(
        y_ptr, w_out, b_out, out, M_ROWS, DOUT, DOUT);
}

// round 17
// speedup vs baseline: 1.2777x; 1.0061x over previous
#include <cuda_runtime.h>
#include <cuda_bf16.h>
#include <cstdint>

// Problem constants
#define BATCH 2
#define SEQ   2048
#define DIN   1024
#define DOUT  1024
#define NHEAD 16
#define HDIM  64
#define M_ROWS (BATCH * SEQ)          // 4096
#define QKV_COLS (3 * DOUT)           // 3072

// Scratch (device globals; no runtime allocation allowed)
__device__ float g_qkv[(size_t)M_ROWS * QKV_COLS];   // tf32-rounded, Q pre-scaled
__device__ float g_y[(size_t)M_ROWS * DOUT];         // tf32-rounded

// ---------------------------------------------------------------------------
// PTX helpers
// ---------------------------------------------------------------------------
__device__ __forceinline__ void cp_async16(void* smem, const void* gmem) {
    uint32_t s = (uint32_t)__cvta_generic_to_shared(smem);
    asm volatile("cp.async.cg.shared.global [%0], [%1], 16;\n" :: "r"(s), "l"(gmem));
}
__device__ __forceinline__ void cp_commit() {
    asm volatile("cp.async.commit_group;\n");
}
template <int N>
__device__ __forceinline__ void cp_wait() {
    asm volatile("cp.async.wait_group %0;\n" :: "n"(N));
}
__device__ __forceinline__ uint32_t f2tf(float f) {
    uint32_t r;
    asm("cvt.rna.tf32.f32 %0, %1;" : "=r"(r) : "f"(f));
    return r;
}
__device__ __forceinline__ float tf32r(float f) {
    return __uint_as_float(f2tf(f));
}
__device__ __forceinline__ float ex2(float x) {
    float y;
    asm("ex2.approx.f32 %0, %1;" : "=f"(y) : "f"(x));
    return y;
}
__device__ __forceinline__ float rcp(float x) {
    float y;
    asm("rcp.approx.f32 %0, %1;" : "=f"(y) : "f"(x));
    return y;
}
__device__ __forceinline__ void mma_tf32(float c[4],
                                         const uint32_t a[4],
                                         const uint32_t b[2]) {
    asm volatile(
        "mma.sync.aligned.m16n8k8.row.col.f32.tf32.tf32.f32 "
        "{%0,%1,%2,%3}, {%4,%5,%6,%7}, {%8,%9}, {%0,%1,%2,%3};\n"
        : "+f"(c[0]), "+f"(c[1]), "+f"(c[2]), "+f"(c[3])
        : "r"(a[0]), "r"(a[1]), "r"(a[2]), "r"(a[3]), "r"(b[0]), "r"(b[1]));
}

// ---------------------------------------------------------------------------
// TF32 tensor-core GEMM: C[M,N] = A[M,K] @ B[N,K]^T (+bias)
// R7/R11/R13/R14/R15/R16 EXACT (measured best ~197us).
// ---------------------------------------------------------------------------
#define BM 128
#define BN 128
#define BK 16
#define GST 20                       // BK + 4 pad
#define STAGE_FLOATS (2 * BM * GST)  // 5120 floats
#define NSTAGE 3
#define GEMM_SMEM_BYTES (NSTAGE * STAGE_FLOATS * 4)   // 61440 B

template <bool BIAS, bool ROUND, bool QSCALE>
__global__ __launch_bounds__(256, 2) void gemm_tf32_nt(
    const float* __restrict__ A, const float* __restrict__ B,
    const float* __restrict__ bias, float* __restrict__ C,
    int M, int N, int K)
{
    extern __shared__ float sm[];

    const int tid  = threadIdx.x;
    const int lane = tid & 31;
    const int warp = tid >> 5;
    const int wm = warp & 1;          // 2 warps along M (64 rows each)
    const int wn = warp >> 1;         // 4 warps along N (32 cols each)
    const int g  = lane >> 2;
    const int tg = lane & 3;

    const int bm = blockIdx.y * BM;
    const int bn = blockIdx.x * BN;

    const int ldr = tid >> 2;          // 0..63
    const int ldc = (tid & 3) * 4;     // 0,4,8,12

    const float* Ag0 = A + (size_t)(bm + ldr) * K + ldc;
    const float* Ag1 = A + (size_t)(bm + ldr + 64) * K + ldc;
    const float* Bg0 = B + (size_t)(bn + ldr) * K + ldc;
    const float* Bg1 = B + (size_t)(bn + ldr + 64) * K + ldc;

    auto load_stage = [&](int s, int ko) {
        float* As = sm + s * STAGE_FLOATS;
        float* Bs = As + BM * GST;
        cp_async16(As + ldr * GST + ldc,        Ag0 + ko);
        cp_async16(As + (ldr + 64) * GST + ldc, Ag1 + ko);
        cp_async16(Bs + ldr * GST + ldc,        Bg0 + ko);
        cp_async16(Bs + (ldr + 64) * GST + ldc, Bg1 + ko);
        cp_commit();
    };

    float acc[4][4][4];
#pragma unroll
    for (int mt = 0; mt < 4; mt++)
#pragma unroll
        for (int nt = 0; nt < 4; nt++)
#pragma unroll
            for (int i = 0; i < 4; i++) acc[mt][nt][i] = 0.f;

    const int nstages = K / BK;

    load_stage(0, 0);
    load_stage(1, BK);

    for (int it = 0; it < nstages; it++) {
        if (it + 1 < nstages) cp_wait<1>();
        else                  cp_wait<0>();
        __syncthreads();

        if (it + 2 < nstages)
            load_stage((it + 2) % NSTAGE, (it + 2) * BK);

        const float* Ab = sm + (it % NSTAGE) * STAGE_FLOATS;
        const float* Bb = Ab + BM * GST;

#pragma unroll
        for (int ks = 0; ks < BK; ks += 8) {
            uint32_t af[4][4], bf[4][2];
#pragma unroll
            for (int mt = 0; mt < 4; mt++) {
                const int m = wm * 64 + mt * 16;
                af[mt][0] = f2tf(Ab[(m + g) * GST + ks + tg]);
                af[mt][1] = f2tf(Ab[(m + g + 8) * GST + ks + tg]);
                af[mt][2] = f2tf(Ab[(m + g) * GST + ks + tg + 4]);
                af[mt][3] = f2tf(Ab[(m + g + 8) * GST + ks + tg + 4]);
            }
#pragma unroll
            for (int nt = 0; nt < 4; nt++) {
                const int n = wn * 32 + nt * 8;
                bf[nt][0] = f2tf(Bb[(n + g) * GST + ks + tg]);
                bf[nt][1] = f2tf(Bb[(n + g) * GST + ks + tg + 4]);
            }
#pragma unroll
            for (int mt = 0; mt < 4; mt++)
#pragma unroll
                for (int nt = 0; nt < 4; nt++)
                    mma_tf32(acc[mt][nt], af[mt], bf[nt]);
        }
    }

    const float qsc = 0.125f * 1.4426950408889634f;

#pragma unroll
    for (int mt = 0; mt < 4; mt++) {
        const int row0 = bm + wm * 64 + mt * 16 + g;
#pragma unroll
        for (int nt = 0; nt < 4; nt++) {
            const int col = bn + wn * 32 + nt * 8 + 2 * tg;
            float v0 = acc[mt][nt][0], v1 = acc[mt][nt][1];
            float v2 = acc[mt][nt][2], v3 = acc[mt][nt][3];
            if (QSCALE && col < DOUT) { v0 *= qsc; v1 *= qsc; v2 *= qsc; v3 *= qsc; }
            if (BIAS) {
                float b0 = bias[col], b1 = bias[col + 1];
                v0 += b0; v1 += b1; v2 += b0; v3 += b1;
            }
            if (ROUND) {
                v0 = tf32r(v0); v1 = tf32r(v1);
                v2 = tf32r(v2); v3 = tf32r(v3);
            }
            *(float2*)(C + (size_t)row0 * N + col) = make_float2(v0, v1);
            *(float2*)(C + (size_t)(row0 + 8) * N + col) = make_float2(v2, v3);
        }
    }
}

// ---------------------------------------------------------------------------
// Flash attention (causal), tf32 mma, register-direct P@V, 128-wide kv tiles,
// d-relabeled LDS.128 K loads (R16).
// NEW: P fed to the P@V mma as RAW fp32 bits (HW truncates to tf32) —
// removes 64 cvt.rna per thread per kv-tile. Only P's rounding mode changes
// (RNA -> truncation); Q/K/V remain pre-rounded upstream.
// ---------------------------------------------------------------------------
#define KS_ST 80
#define VS_ST 68
#define FSTAGE (128 * KS_ST + 128 * VS_ST)   // floats per stage (K+V)
#define FNSTAGE 3
#define FLASH_SMEM_BYTES (FNSTAGE * FSTAGE * 4)   // 227328 B

__global__ __launch_bounds__(256, 1) void flash_mma_kernel(
    const float* __restrict__ qkv, float* __restrict__ y)
{
    extern __shared__ float sm[];

    const int qi = (int)gridDim.x - 1 - (int)blockIdx.x;  // heavy tiles first
    const int bh = blockIdx.y;
    const int b  = bh >> 4;
    const int h  = bh & 15;
    const int qbase = qi * 128;

    const float* base = qkv + (size_t)b * SEQ * QKV_COLS;
    const int hoff = h * HDIM;

    const int tid  = threadIdx.x;
    const int lane = tid & 31;
    const int warp = tid >> 5;
    const int g  = lane >> 2;
    const int tg = lane & 3;
    const int w16 = warp * 16;

    // --- stage Q into stage-0 K region (dead after aq regs built) ---
    float (*Qs)[KS_ST] = (float(*)[KS_ST])sm;
    for (int i = tid; i < 128 * 16; i += 256) {
        int r  = i >> 4;
        int c4 = (i & 15) * 4;
        float4 v = *(const float4*)(base + (size_t)(qbase + r) * QKV_COLS + hoff + c4);
        *(float4*)&Qs[r][c4] = v;
    }
    __syncthreads();

    // A-fragments with d-relabel: group 2j k-slot tg -> d=16j+4tg,
    // slot tg+4 -> d=16j+4tg+1; group 2j+1 -> +2,+3.
    uint32_t aq[8][4];
#pragma unroll
    for (int j = 0; j < 4; j++) {
        float4 q0 = *(const float4*)&Qs[w16 + g][16 * j + 4 * tg];
        float4 q1 = *(const float4*)&Qs[w16 + g + 8][16 * j + 4 * tg];
        aq[2 * j][0] = __float_as_uint(q0.x);
        aq[2 * j][1] = __float_as_uint(q1.x);
        aq[2 * j][2] = __float_as_uint(q0.y);
        aq[2 * j][3] = __float_as_uint(q1.y);
        aq[2 * j + 1][0] = __float_as_uint(q0.z);
        aq[2 * j + 1][1] = __float_as_uint(q1.z);
        aq[2 * j + 1][2] = __float_as_uint(q0.w);
        aq[2 * j + 1][3] = __float_as_uint(q1.w);
    }
    __syncthreads();   // Q region dead; safe for K/V prefetch to overwrite

    float O[8][4];
#pragma unroll
    for (int n = 0; n < 8; n++)
#pragma unroll
        for (int i = 0; i < 4; i++) O[n][i] = 0.f;
    float m0 = -1e30f, m1 = -1e30f, l0 = 0.f, l1 = 0.f;

    const int njt = qi + 1;   // 128-wide kv tiles

    auto prefetch = [&](int jt, int stage) {
        const int jb = jt * 128;
        float* Ks = sm + stage * FSTAGE;
        float* Vs = Ks + 128 * KS_ST;
        for (int i = tid; i < 128 * 16; i += 256) {
            int r  = i >> 4;
            int c4 = (i & 15) * 4;
            const float* rowp = base + (size_t)(jb + r) * QKV_COLS + hoff;
            cp_async16(Ks + r * KS_ST + c4, rowp + DOUT + c4);
            cp_async16(Vs + r * VS_ST + c4, rowp + 2 * DOUT + c4);
        }
        cp_commit();
    };

    prefetch(0, 0);
    if (njt > 1) prefetch(1, 1);

    for (int jt = 0; jt < njt; jt++) {
        if (jt + 1 < njt) cp_wait<1>();
        else              cp_wait<0>();
        __syncthreads();   // stage jt visible; all warps done with jt-1

        if (jt + 2 < njt)
            prefetch(jt + 2, (jt + 2) % FNSTAGE);

        const float* Ks = sm + (jt % FNSTAGE) * FSTAGE;
        const float* Vs = Ks + 128 * KS_ST;

        // ---- S = Qhat @ K^T  (16x128 per warp), vectorized K loads ----
        float S[16][4];
#pragma unroll
        for (int n = 0; n < 16; n++)
#pragma unroll
            for (int i = 0; i < 4; i++) S[n][i] = 0.f;

#pragma unroll
        for (int j = 0; j < 4; j++) {
#pragma unroll
            for (int n = 0; n < 16; n++) {
                float4 kf = *(const float4*)&Ks[(n * 8 + g) * KS_ST + 16 * j + 4 * tg];
                uint32_t kb0[2] = {__float_as_uint(kf.x), __float_as_uint(kf.y)};
                uint32_t kb1[2] = {__float_as_uint(kf.z), __float_as_uint(kf.w)};
                mma_tf32(S[n], aq[2 * j], kb0);
                mma_tf32(S[n], aq[2 * j + 1], kb1);
            }
        }

        // ---- causal mask (diagonal tile only) ----
        if (jt == qi) {
            const int r0 = qbase + w16 + g;
            const int r1 = r0 + 8;
            const int cb = jt * 128 + 2 * tg;
#pragma unroll
            for (int n = 0; n < 16; n++) {
                const int c0 = cb + n * 8;
                if (c0 > r0)     S[n][0] = -1e30f;
                if (c0 + 1 > r0) S[n][1] = -1e30f;
                if (c0 > r1)     S[n][2] = -1e30f;
                if (c0 + 1 > r1) S[n][3] = -1e30f;
            }
        }

        // ---- online softmax (base-2); one pass per 128 kv cols ----
        float rm0 = -1e30f, rm1 = -1e30f;
#pragma unroll
        for (int n = 0; n < 16; n++) {
            rm0 = fmaxf(rm0, fmaxf(S[n][0], S[n][1]));
            rm1 = fmaxf(rm1, fmaxf(S[n][2], S[n][3]));
        }
        rm0 = fmaxf(rm0, __shfl_xor_sync(0xffffffffu, rm0, 1));
        rm0 = fmaxf(rm0, __shfl_xor_sync(0xffffffffu, rm0, 2));
        rm1 = fmaxf(rm1, __shfl_xor_sync(0xffffffffu, rm1, 1));
        rm1 = fmaxf(rm1, __shfl_xor_sync(0xffffffffu, rm1, 2));

        const float mn0 = fmaxf(m0, rm0);
        const float mn1 = fmaxf(m1, rm1);
        const float corr0 = ex2(m0 - mn0);
        const float corr1 = ex2(m1 - mn1);
        m0 = mn0; m1 = mn1;

        float rs0 = 0.f, rs1 = 0.f;
#pragma unroll
        for (int n = 0; n < 16; n++) {
            float p0 = ex2(S[n][0] - mn0);
            float p1 = ex2(S[n][1] - mn0);
            float p2 = ex2(S[n][2] - mn1);
            float p3 = ex2(S[n][3] - mn1);
            rs0 += p0 + p1;
            rs1 += p2 + p3;
            S[n][0] = p0; S[n][1] = p1; S[n][2] = p2; S[n][3] = p3;
        }
#pragma unroll
        for (int n = 0; n < 8; n++) {
            O[n][0] *= corr0; O[n][1] *= corr0;
            O[n][2] *= corr1; O[n][3] *= corr1;
        }
        rs0 += __shfl_xor_sync(0xffffffffu, rs0, 1);
        rs0 += __shfl_xor_sync(0xffffffffu, rs0, 2);
        rs1 += __shfl_xor_sync(0xffffffffu, rs1, 1);
        rs1 += __shfl_xor_sync(0xffffffffu, rs1, 2);
        l0 = l0 * corr0 + rs0;
        l1 = l1 * corr1 + rs1;

        // ---- O += P @ V, P raw fp32 bits (HW tf32 truncation) ----
#pragma unroll
        for (int n = 0; n < 16; n++) {
            uint32_t pa[4];
            pa[0] = __float_as_uint(S[n][0]);
            pa[1] = __float_as_uint(S[n][2]);
            pa[2] = __float_as_uint(S[n][1]);
            pa[3] = __float_as_uint(S[n][3]);
#pragma unroll
            for (int nn = 0; nn < 8; nn++) {
                uint32_t vb[2];
                vb[0] = __float_as_uint(Vs[(n * 8 + 2 * tg) * VS_ST + nn * 8 + g]);
                vb[1] = __float_as_uint(Vs[(n * 8 + 2 * tg + 1) * VS_ST + nn * 8 + g]);
                mma_tf32(O[nn], pa, vb);
            }
        }
        // no trailing barrier: next tile's barrier protects stage reuse
    }

    const float inv0 = rcp(l0);
    const float inv1 = rcp(l1);
    const int r0 = qbase + w16 + g;
    float* yr0 = y + (size_t)b * SEQ * DOUT + (size_t)r0 * DOUT + hoff;
    float* yr1 = yr0 + 8 * DOUT;
#pragma unroll
    for (int n = 0; n < 8; n++) {
        const int c = n * 8 + 2 * tg;
        *(float2*)(yr0 + c) = make_float2(tf32r(O[n][0] * inv0), tf32r(O[n][1] * inv0));
        *(float2*)(yr1 + c) = make_float2(tf32r(O[n][2] * inv1), tf32r(O[n][3] * inv1));
    }
}

// ---------------------------------------------------------------------------
extern "C" void kernel_launch(void* const* d_in, const int* in_sizes, int n_in,
                              void* d_out, int out_size)
{
    const float* x     = (const float*)d_in[0];
    const float* w_qkv = (const float*)d_in[1];
    const float* w_out = (const float*)d_in[2];
    const float* b_out = (const float*)d_in[3];
    float* out = (float*)d_out;

    float *qkv_ptr, *y_ptr;
    cudaGetSymbolAddress((void**)&qkv_ptr, g_qkv);
    cudaGetSymbolAddress((void**)&y_ptr, g_y);

    cudaFuncSetAttribute(gemm_tf32_nt<false, true, true>,
                         cudaFuncAttributeMaxDynamicSharedMemorySize,
                         GEMM_SMEM_BYTES);
    cudaFuncSetAttribute(gemm_tf32_nt<true, false, false>,
                         cudaFuncAttributeMaxDynamicSharedMemorySize,
                         GEMM_SMEM_BYTES);
    cudaFuncSetAttribute(flash_mma_kernel,
                         cudaFuncAttributeMaxDynamicSharedMemorySize,
                         FLASH_SMEM_BYTES);

    // 1) QKV projection (output tf32-rounded, Q pre-scaled by 0.125*log2e)
    gemm_tf32_nt<false, true, true>
        <<<dim3(QKV_COLS / BN, M_ROWS / BM), 256, GEMM_SMEM_BYTES>>>(
        x, w_qkv, nullptr, qkv_ptr, M_ROWS, QKV_COLS, DIN);

    // 2) Flash attention (y stored tf32-rounded)
    flash_mma_kernel<<<dim3(SEQ / 128, BATCH * NHEAD), 256, FLASH_SMEM_BYTES>>>(
        qkv_ptr, y_ptr);

    // 3) Output projection + bias (final fp32 output)
    gemm_tf32_nt<true, false, false>
        <<<dim3(DOUT / BN, M_ROWS / BM), 256, GEMM_SMEM_BYTES>>>(
        y_ptr, w_out, b_out, out, M_ROWS, DOUT, DOUT);
}